// round 14
// baseline (speedup 1.0000x reference)
#include <cuda_runtime.h>
#include <cuda_fp16.h>
#include <math.h>
#include <stdint.h>

// ---------------------------------------------------------------------------
// Problem constants: B=2, C=256, H=W=256, SSM=256, NH=16, HD=16, WS=8
// ---------------------------------------------------------------------------
#define PPLANE 65536
#define NBATCH 2
#define YSZ (NBATCH * 256 * PPLANE)

typedef unsigned long long u64;
typedef unsigned short u16;

__device__ u16 g_lh   [NBATCH * 256 * PPLANE];     // local branch out (fp16)
__device__ u16 g_qkvh [NBATCH * 768 * PPLANE];     // fp16, window-major pixels
__device__ u16 g_attnh[NBATCH * 256 * PPLANE];     // fp16 attention output

// pre-converted fp16 operands
__device__ u16 g_xh [NBATCH * 256 * PPLANE];
__device__ u16 g_ysh[3 * YSZ];                     // y shifted dx=-1,0,+1
__device__ u16 g_dwh[NBATCH * 256 * PPLANE];
__device__ u16 g_wqh [768 * 256];
__device__ u16 g_wph [256 * 256];
__device__ u16 g_wlh [256 * 2560];

__device__ float g_inv1[256], g_inv2[256], g_biasc[256], g_invp[256], g_biasp[256];

// ---------------------------------------------------------------------------
// helpers
// ---------------------------------------------------------------------------
__device__ __forceinline__ uint32_t smem_u32(const void* p) {
    uint32_t a;
    asm("{ .reg .u64 t; cvta.to.shared.u64 t, %1; cvt.u32.u64 %0, t; }"
        : "=r"(a) : "l"(p));
    return a;
}
__device__ __forceinline__ u16 h16(float v) {
    __half h = __float2half_rn(v);
    return *reinterpret_cast<u16*>(&h);
}
__device__ __forceinline__ float f16f(u16 v) {
    __half h = *reinterpret_cast<__half*>(&v);
    return __half2float(h);
}
__device__ __forceinline__ uint32_t h2bits(float a, float b) {
    __half2 h = __floats2half2_rn(a, b);
    return *reinterpret_cast<uint32_t*>(&h);
}
__device__ __forceinline__ void ldsm4(uint32_t* r, uint32_t a) {
    asm volatile("ldmatrix.sync.aligned.m8n8.x4.shared.b16 {%0,%1,%2,%3},[%4];"
                 : "=r"(r[0]), "=r"(r[1]), "=r"(r[2]), "=r"(r[3]) : "r"(a));
}
__device__ __forceinline__ void ldsm4t(uint32_t* r, uint32_t a) {
    asm volatile("ldmatrix.sync.aligned.m8n8.x4.trans.shared.b16 {%0,%1,%2,%3},[%4];"
                 : "=r"(r[0]), "=r"(r[1]), "=r"(r[2]), "=r"(r[3]) : "r"(a));
}
__device__ __forceinline__ void mma16(float* c, const uint32_t* a, const uint32_t* b) {
    asm volatile(
        "mma.sync.aligned.m16n8k16.row.col.f32.f16.f16.f32 "
        "{%0,%1,%2,%3},{%4,%5,%6,%7},{%8,%9},{%0,%1,%2,%3};"
        : "+f"(c[0]), "+f"(c[1]), "+f"(c[2]), "+f"(c[3])
        : "r"(a[0]), "r"(a[1]), "r"(a[2]), "r"(a[3]), "r"(b[0]), "r"(b[1]));
}

#define ASTRIDE 48
#define BSTRIDE 272
#define ABYTES (128 * ASTRIDE)
#define BBYTES (16 * BSTRIDE)

__device__ __forceinline__ int perm_px(int p) {
    int h = p >> 8, w = p & 255;
    return (((h >> 3) * 32 + (w >> 3)) << 6) + ((h & 7) << 3) + (w & 7);
}

// ---------------------------------------------------------------------------
// Prep kernels
// ---------------------------------------------------------------------------
__global__ void prep_kernel(const float* __restrict__ g1, const float* __restrict__ b1,
                            const float* __restrict__ m1, const float* __restrict__ v1,
                            const float* __restrict__ g2, const float* __restrict__ b2,
                            const float* __restrict__ m2, const float* __restrict__ v2,
                            const float* __restrict__ gp, const float* __restrict__ bp,
                            const float* __restrict__ mp, const float* __restrict__ vp)
{
    int c = threadIdx.x;
    float i1 = g1[c] * rsqrtf(v1[c] + 1e-5f);
    float i2 = g2[c] * rsqrtf(v2[c] + 1e-5f);
    g_inv1[c] = i1;
    g_inv2[c] = i2;
    g_biasc[c] = (b1[c] - m1[c] * i1) + (b2[c] - m2[c] * i2);
    float ip = gp[c] * rsqrtf(vp[c] + 1e-5f);
    g_invp[c] = ip;
    g_biasp[c] = bp[c] - mp[c] * ip;
}

__global__ void cvt_wqkv(const float* __restrict__ w)
{
    int i = blockIdx.x * 256 + threadIdx.x;
    if (i >= 768 * 256) return;
    float sc = (i < 256 * 256) ? 0.25f : 1.0f;
    g_wqh[i] = h16(w[i] * sc);
}
__global__ void cvt_wpw(const float* __restrict__ w)
{
    int i = blockIdx.x * 256 + threadIdx.x;
    g_wph[i] = h16(w[i]);
}
__global__ void cvt_wlocal(const float* __restrict__ w1, const float* __restrict__ w2)
{
    int i = blockIdx.x * 256 + threadIdx.x;
    if (i >= 256 * 2560) return;
    int m = i / 2560, k = i - m * 2560;
    float v = (k < 2304) ? w1[m * 2304 + k] * g_inv1[m]
                         : w2[m * 256 + (k - 2304)] * g_inv2[m];
    g_wlh[i] = h16(v);
}
__global__ void cvt_x(const float* __restrict__ x)
{
    size_t base = ((size_t)blockIdx.x * 256 + threadIdx.x) * 4;
    float4 v = *(const float4*)(x + base);
    u16 h[4] = { h16(v.x), h16(v.y), h16(v.z), h16(v.w) };
    *(uint2*)(g_xh + base) = *(uint2*)h;
}
// y -> 3 shifted fp16 copies (dx = -1, 0, +1), zero at row edges
__global__ void cvt_y(const float* __restrict__ y)
{
    size_t base = ((size_t)blockIdx.x * 256 + threadIdx.x) * 4;
    int w0 = (int)(base & 255);
    float4 v = *(const float4*)(y + base);
    float vm = (w0 > 0)   ? y[base - 1] : 0.f;     // y[w0-1]
    float vp = (w0 < 252) ? y[base + 4] : 0.f;     // y[w0+4]
    if (w0 == 252) vp = 0.f;

    // dx = 0
    u16 c1[4] = { h16(v.x), h16(v.y), h16(v.z), h16(v.w) };
    *(uint2*)(g_ysh + YSZ + base) = *(uint2*)c1;
    // dx = -1: out[i] = y[i-1]
    u16 c0[4] = { h16(vm), c1[0], c1[1], c1[2] };
    *(uint2*)(g_ysh + base) = *(uint2*)c0;
    // dx = +1: out[i] = y[i+1]  (w0+3 -> y[w0+4]; last elem of row -> 0)
    u16 c2[4] = { c1[1], c1[2], c1[3], (w0 == 252) ? (u16)0 : h16(vp) };
    if (w0 == 252) c2[3] = 0;
    *(uint2*)(g_ysh + 2 * (size_t)YSZ + base) = *(uint2*)c2;
}

// ---------------------------------------------------------------------------
// Consumer: one K=16 step, 1-pass fp16.
// ---------------------------------------------------------------------------
__device__ __forceinline__ void mma_step(
    uint32_t sAh, uint32_t sB,
    int wm, int wn, int lane, float acc[4][4][4])
{
    int t  = lane >> 3;
    int r8 = lane & 7;
    uint32_t bh[4][2];
#pragma unroll
    for (int ng = 0; ng < 2; ++ng) {
        uint32_t addr = ((t >> 1) * 8 + r8) * BSTRIDE + (wn + ng * 16 + (t & 1) * 8) * 2;
        uint32_t tb[4];
        ldsm4t(tb, sB + addr);
        bh[ng * 2 + 0][0] = tb[0]; bh[ng * 2 + 0][1] = tb[2];
        bh[ng * 2 + 1][0] = tb[1]; bh[ng * 2 + 1][1] = tb[3];
    }
    uint32_t abase = ((t & 1) * 8 + r8) * ASTRIDE + (t >> 1) * 16;
#pragma unroll
    for (int mt = 0; mt < 4; ++mt) {
        uint32_t arow = abase + (wm + mt * 16) * ASTRIDE;
        uint32_t ah[4];
        ldsm4(ah, sAh + arow);
#pragma unroll
        for (int j = 0; j < 4; ++j) mma16(acc[mt][j], ah, bh[j]);
    }
}

// ---------------------------------------------------------------------------
// Aligned GEMM, 1-pass fp16, operands device-side.
//   which==0: A = wqkv (M=768,K=256), B = x,  C = g_qkvh (fp16, permuted)
//   which==1: A = wpw  (M=256,K=256), B = dw, C = extC (fp32)
// grid = (M/128, 1024)
// ---------------------------------------------------------------------------
__global__ __launch_bounds__(256, 2) void gemm_aligned(float* extC, int M, int K, int which)
{
    __shared__ __align__(16) char AhS[2][ABYTES];
    __shared__ __align__(16) char BS [2][BBYTES];

    const u16 *Ah_g, *B_g;
    if (which == 0) { Ah_g = g_wqh; B_g = g_xh; }
    else            { Ah_g = g_wph; B_g = g_dwh; }

    int tid = threadIdx.x;
    int m0  = blockIdx.x * 128;
    int pg0 = blockIdx.y * 128;
    int b   = pg0 >> 16;
    int p0  = pg0 & 65535;
    int lane = tid & 31, warp = tid >> 5;
    int wm = (warp >> 2) * 64, wn = (warp & 3) * 32;

    int am = tid >> 1, ak = (tid & 1) * 8;
    const u16* Abh = Ah_g + (size_t)(m0 + am) * K + ak;
    int bk = tid >> 4, bn = (tid & 15) * 8;
    size_t bbase = ((size_t)(b * K + bk) << 16) + p0 + bn;

    int aoff = am * ASTRIDE + ak * 2;
    int boff = bk * BSTRIDE + bn * 2;

    float acc[4][4][4];
#pragma unroll
    for (int i = 0; i < 4; ++i)
#pragma unroll
        for (int j = 0; j < 4; ++j)
#pragma unroll
            for (int r = 0; r < 4; ++r) acc[i][j][r] = 0.f;

    uint4 rah, rb;
    auto gload = [&](int k0) {
        rah = *(const uint4*)(Abh + k0);
        rb  = *(const uint4*)(B_g + bbase + ((size_t)k0 << 16));
    };
    auto sstore = [&](int s) {
        *(uint4*)(AhS[s] + aoff) = rah;
        *(uint4*)(BS[s]  + boff) = rb;
    };

    int nch = K >> 4;
    gload(0);
    sstore(0);
    if (nch > 1) gload(16);
    __syncthreads();

    for (int ch = 0; ch < nch; ++ch) {
        if (ch + 1 < nch) sstore((ch + 1) & 1);
        if (ch + 2 < nch) gload((ch + 2) << 4);
        int s = ch & 1;
        mma_step(smem_u32(AhS[s]), smem_u32(BS[s]), wm, wn, lane, acc);
        __syncthreads();
    }

    int g = lane >> 2, tig = lane & 3;
#pragma unroll
    for (int mt = 0; mt < 4; ++mt) {
        int r0 = m0 + wm + mt * 16 + g;
#pragma unroll
        for (int j = 0; j < 4; ++j) {
            int col = p0 + wn + j * 8 + tig * 2;
            if (which == 0) {
                int pc = perm_px(col);
                size_t i0 = ((size_t)(b * M + r0) << 16) + pc;
                size_t i1 = ((size_t)(b * M + r0 + 8) << 16) + pc;
                *(uint32_t*)&g_qkvh[i0] = h2bits(acc[mt][j][0], acc[mt][j][1]);
                *(uint32_t*)&g_qkvh[i1] = h2bits(acc[mt][j][2], acc[mt][j][3]);
            } else {
                size_t i0 = ((size_t)(b * M + r0) << 16) + col;
                size_t i1 = ((size_t)(b * M + r0 + 8) << 16) + col;
                *(float2*)&extC[i0] = make_float2(acc[mt][j][0], acc[mt][j][1]);
                *(float2*)&extC[i1] = make_float2(acc[mt][j][2], acc[mt][j][3]);
            }
        }
    }
}

// ---------------------------------------------------------------------------
// Fused local branch GEMM (1-pass fp16), K=2560, B = aligned loads from the
// pre-shifted y copies.  grid = (2, 1024).  Output fp16 (+bias) -> g_lh.
// ---------------------------------------------------------------------------
__global__ __launch_bounds__(256, 2) void gemm_local_f16(void)
{
    __shared__ __align__(16) char AhS[2][ABYTES];
    __shared__ __align__(16) char BS [2][BBYTES];

    int tid = threadIdx.x;
    int m0  = blockIdx.x * 128;
    int pg0 = blockIdx.y * 128;
    int b   = pg0 >> 16;
    int p0  = pg0 & 65535;
    int h   = p0 >> 8;
    int w0  = p0 & 255;
    int lane = tid & 31, warp = tid >> 5;
    int wm = (warp >> 2) * 64, wn = (warp & 3) * 32;

    int am = tid >> 1, ak = (tid & 1) * 8;
    int mg = m0 + am;
    int bk = tid >> 4, bn = (tid & 15) * 8;

    int aoff = am * ASTRIDE + ak * 2;
    int boff = bk * BSTRIDE + bn * 2;

    const u16* Abh = g_wlh + (size_t)mg * 2560 + ak;

    float acc[4][4][4];
#pragma unroll
    for (int i = 0; i < 4; ++i)
#pragma unroll
        for (int j = 0; j < 4; ++j)
#pragma unroll
            for (int r = 0; r < 4; ++r) acc[i][j][r] = 0.f;

    uint4 rah, rb;
    auto gload = [&](int k0) {
        rah = *(const uint4*)(Abh + k0);
        int k = k0 + bk;
        int ci, dy, dx;
        if (k < 2304) {
            ci = k / 9;
            int tap = k - ci * 9;
            int r = tap / 3;
            dy = r - 1;
            dx = tap - r * 3 - 1;
        } else { ci = k - 2304; dy = 0; dx = 1 - 1; dx = 0; }
        int hh = h + dy;
        if (hh >= 0 && hh < 256) {
            const u16* row = g_ysh + (size_t)(dx + 1) * YSZ
                           + ((size_t)(b * 256 + ci) << 16) + hh * 256 + w0 + bn;
            rb = *(const uint4*)row;
        } else {
            rb = make_uint4(0u, 0u, 0u, 0u);
        }
    };
    auto sstore = [&](int s) {
        *(uint4*)(AhS[s] + aoff) = rah;
        *(uint4*)(BS[s]  + boff) = rb;
    };

    const int nch = 160;
    gload(0);
    sstore(0);
    gload(16);
    __syncthreads();

    for (int ch = 0; ch < nch; ++ch) {
        if (ch + 1 < nch) sstore((ch + 1) & 1);
        if (ch + 2 < nch) gload((ch + 2) << 4);
        int s = ch & 1;
        mma_step(smem_u32(AhS[s]), smem_u32(BS[s]), wm, wn, lane, acc);
        __syncthreads();
    }

    int g = lane >> 2, tig = lane & 3;
#pragma unroll
    for (int mt = 0; mt < 4; ++mt) {
        int r0 = m0 + wm + mt * 16 + g;
        float bi0 = g_biasc[r0];
        float bi1 = g_biasc[r0 + 8];
#pragma unroll
        for (int j = 0; j < 4; ++j) {
            int col = p0 + wn + j * 8 + tig * 2;
            size_t i0 = ((size_t)(b * 256 + r0) << 16) + col;
            size_t i1 = ((size_t)(b * 256 + r0 + 8) << 16) + col;
            *(uint32_t*)&g_lh[i0] = h2bits(acc[mt][j][0] + bi0, acc[mt][j][1] + bi0);
            *(uint32_t*)&g_lh[i1] = h2bits(acc[mt][j][2] + bi1, acc[mt][j][3] + bi1);
        }
    }
}

// ---------------------------------------------------------------------------
// Tensor-core windowed attention: 1 warp = 1 (window, head). fp16 output.
// ---------------------------------------------------------------------------
#define QSTR 72

__global__ __launch_bounds__(128) void attn_mma(const float* __restrict__ rpb)
{
    __shared__ u16 qkvS[4][48][QSTR];
    __shared__ float rpbs[225];

    int tid  = threadIdx.x;
    int warp = tid >> 5, lane = tid & 31;
    int head = blockIdx.y;
    int win  = blockIdx.x * 4 + warp;
    int b    = win >> 10;
    int wloc = win & 1023;

    for (int t = tid; t < 225; t += 128) rpbs[t] = rpb[t * 16 + head];

    {
        int ppb = wloc * 64;
        for (int f = lane; f < 768; f += 32) {
            int row = f >> 4;
            int c4  = (f & 15) * 4;
            int ch  = b * 768 + head * 16 + (row & 15) + (row >> 4) * 256;
            uint2 v = *(const uint2*)(g_qkvh + (((size_t)ch) << 16) + ppb + c4);
            *(uint2*)&qkvS[warp][row][c4] = v;
        }
    }
    __syncthreads();

    uint32_t sQ = smem_u32(&qkvS[warp][0][0]);
    uint32_t sK = smem_u32(&qkvS[warp][16][0]);
    uint32_t sV = smem_u32(&qkvS[warp][32][0]);

    int t = lane >> 3, r8 = lane & 7;
    int g = lane >> 2, tig = lane & 3;

    uint32_t bqk[8][2];
#pragma unroll
    for (int ng = 0; ng < 4; ++ng) {
        uint32_t addr = sK + (((t >> 1) * 8 + r8) * QSTR + ng * 16 + (t & 1) * 8) * 2;
        uint32_t tb[4];
        ldsm4t(tb, addr);
        bqk[2 * ng + 0][0] = tb[0]; bqk[2 * ng + 0][1] = tb[2];
        bqk[2 * ng + 1][0] = tb[1]; bqk[2 * ng + 1][1] = tb[3];
    }
    uint32_t bv[4][2][2];
#pragma unroll
    for (int kt = 0; kt < 4; ++kt) {
        uint32_t addr = sV + (((t & 1) * 8 + r8) * QSTR + kt * 16 + (t >> 1) * 8) * 2;
        uint32_t tb[4];
        ldsm4(tb, addr);
        bv[kt][0][0] = tb[0]; bv[kt][0][1] = tb[2];
        bv[kt][1][0] = tb[1]; bv[kt][1][1] = tb[3];
    }

    int wy = wloc >> 5, wx = wloc & 31;

#pragma unroll
    for (int mt = 0; mt < 4; ++mt) {
        uint32_t aQ[4];
        ldsm4t(aQ, sQ + (((t >> 1) * 8 + r8) * QSTR + mt * 16 + (t & 1) * 8) * 2);

        float s[8][4];
#pragma unroll
        for (int nt = 0; nt < 8; ++nt) {
            s[nt][0] = s[nt][1] = s[nt][2] = s[nt][3] = 0.f;
            mma16(s[nt], aQ, bqk[nt]);
        }

        int row0 = mt * 16 + g, row1 = row0 + 8;
        int yi0 = row0 >> 3, xi0 = row0 & 7;
        int yi1 = row1 >> 3, xi1 = row1 & 7;
        float mx0 = -1e30f, mx1 = -1e30f;
#pragma unroll
        for (int nt = 0; nt < 8; ++nt) {
            int col = nt * 8 + tig * 2;
            int yj = col >> 3, xj = col & 7;
            s[nt][0] += rpbs[(yi0 - yj + 7) * 15 + (xi0 - xj + 7)];
            s[nt][1] += rpbs[(yi0 - yj + 7) * 15 + (xi0 - xj + 6)];
            s[nt][2] += rpbs[(yi1 - yj + 7) * 15 + (xi1 - xj + 7)];
            s[nt][3] += rpbs[(yi1 - yj + 7) * 15 + (xi1 - xj + 6)];
            mx0 = fmaxf(mx0, fmaxf(s[nt][0], s[nt][1]));
            mx1 = fmaxf(mx1, fmaxf(s[nt][2], s[nt][3]));
        }
        mx0 = fmaxf(mx0, __shfl_xor_sync(0xffffffffu, mx0, 1));
        mx0 = fmaxf(mx0, __shfl_xor_sync(0xffffffffu, mx0, 2));
        mx1 = fmaxf(mx1, __shfl_xor_sync(0xffffffffu, mx1, 1));
        mx1 = fmaxf(mx1, __shfl_xor_sync(0xffffffffu, mx1, 2));

        float sum0 = 0.f, sum1 = 0.f;
#pragma unroll
        for (int nt = 0; nt < 8; ++nt) {
            s[nt][0] = __expf(s[nt][0] - mx0);
            s[nt][1] = __expf(s[nt][1] - mx0);
            s[nt][2] = __expf(s[nt][2] - mx1);
            s[nt][3] = __expf(s[nt][3] - mx1);
            sum0 += s[nt][0] + s[nt][1];
            sum1 += s[nt][2] + s[nt][3];
        }
        sum0 += __shfl_xor_sync(0xffffffffu, sum0, 1);
        sum0 += __shfl_xor_sync(0xffffffffu, sum0, 2);
        sum1 += __shfl_xor_sync(0xffffffffu, sum1, 1);
        sum1 += __shfl_xor_sync(0xffffffffu, sum1, 2);
        float inv0 = 1.f / sum0, inv1 = 1.f / sum1;

        float o[2][4];
        o[0][0]=o[0][1]=o[0][2]=o[0][3]=0.f;
        o[1][0]=o[1][1]=o[1][2]=o[1][3]=0.f;
#pragma unroll
        for (int kt = 0; kt < 4; ++kt) {
            uint32_t aP[4];
            aP[0] = h2bits(s[2 * kt][0],     s[2 * kt][1]);
            aP[1] = h2bits(s[2 * kt][2],     s[2 * kt][3]);
            aP[2] = h2bits(s[2 * kt + 1][0], s[2 * kt + 1][1]);
            aP[3] = h2bits(s[2 * kt + 1][2], s[2 * kt + 1][3]);
            mma16(o[0], aP, bv[kt][0]);
            mma16(o[1], aP, bv[kt][1]);
        }

        int p0 = ((wy * 8 + yi0) << 8) + wx * 8 + xi0;
        int p1 = ((wy * 8 + yi1) << 8) + wx * 8 + xi1;
#pragma unroll
        for (int nd = 0; nd < 2; ++nd) {
            int ch0 = b * 256 + head * 16 + nd * 8 + tig * 2;
            g_attnh[(((size_t)ch0)     << 16) + p0] = h16(o[nd][0] * inv0);
            g_attnh[(((size_t)ch0 + 1) << 16) + p0] = h16(o[nd][1] * inv0);
            g_attnh[(((size_t)ch0)     << 16) + p1] = h16(o[nd][2] * inv1);
            g_attnh[(((size_t)ch0 + 1) << 16) + p1] = h16(o[nd][3] * inv1);
        }
    }
}

// ---------------------------------------------------------------------------
// Fused pool + depthwise 8x8 conv + BN -> single fp16 output g_dwh.
// ---------------------------------------------------------------------------
__global__ __launch_bounds__(256) void dwpool_kernel(const float* __restrict__ w_dw)
{
    __shared__ float attnS[46][48];
    __shared__ float midS[39][40];
    __shared__ float ws[64];

    int tix = blockIdx.x;
    int bc  = blockIdx.y;
    int c   = bc & 255;
    int ty0 = (tix >> 3) * 32;
    int tx0 = (tix & 7) * 32;
    int tid = threadIdx.x;

    const u16* aplane = g_attnh + ((size_t)bc << 16);
    const u16* lplane = g_lh    + ((size_t)bc << 16);

    for (int idx = tid; idx < 46 * 46; idx += 256) {
        int r  = idx / 46;
        int cc = idx - r * 46;
        int gh = ty0 - 6 + r;
        int gw = tx0 - 6 + cc;
        float v = 0.f;
        if (gh >= 0 && gh < 256 && gw >= 0 && gw < 256) v = f16f(aplane[gh * 256 + gw]);
        attnS[r][cc] = v;
    }
    if (tid < 64) ws[tid] = w_dw[c * 64 + tid];
    __syncthreads();

    for (int idx = tid; idx < 39 * 39; idx += 256) {
        int r  = idx / 39;
        int cc = idx - r * 39;
        int gh = ty0 - 3 + r;
        int gw = tx0 - 3 + cc;
        float v = 0.f;
        if (gh >= 0 && gh <= 256 && gw >= 0 && gw <= 256) {
            int gh2 = (gh == 256) ? 254 : gh;
            int gw2 = (gw == 256) ? 254 : gw;
            int co = gw2 - (tx0 - 6);
            float vs = 0.f;
#pragma unroll
            for (int tt2 = gh2 - 3; tt2 <= gh2 + 4; ++tt2) {
                if (tt2 >= 0 && tt2 <= 256) {
                    int tt = (tt2 == 256) ? 254 : tt2;
                    vs += attnS[tt - (ty0 - 6)][co];
                }
            }
            int ro = gh2 - (ty0 - 6);
            float hs = 0.f;
#pragma unroll
            for (int ss2 = gw2 - 3; ss2 <= gw2 + 4; ++ss2) {
                if (ss2 >= 0 && ss2 <= 256) {
                    int ss = (ss2 == 256) ? 254 : ss2;
                    hs += attnS[ro][ss - (tx0 - 6)];
                }
            }
            v = (vs + hs) * 0.125f + f16f(lplane[gh2 * 256 + gw2]);
        }
        midS[r][cc] = v;
    }
    __syncthreads();

    int lw  = tid & 31;
    int lh0 = (tid >> 5) * 4;
    float acc[4] = {0.f, 0.f, 0.f, 0.f};
#pragma unroll
    for (int j = 0; j < 8; ++j) {
        float wcol[8];
#pragma unroll
        for (int i = 0; i < 8; ++i) wcol[i] = ws[i * 8 + j];
#pragma unroll
        for (int r = 0; r < 11; ++r) {
            float v = midS[lh0 + r][lw + j];
#pragma unroll
            for (int a = 0; a < 4; ++a) {
                int i = r - a;
                if (i >= 0 && i < 8) acc[a] += v * wcol[i];
            }
        }
    }
    float ip = g_invp[c];
    float bb = g_biasp[c];
#pragma unroll
    for (int a = 0; a < 4; ++a) {
        int h = ty0 + lh0 + a;
        float r = acc[a] * ip + bb;
        size_t idx = ((size_t)bc << 16) + h * 256 + tx0 + lw;
        g_dwh[idx] = h16(r);
    }
}

// ---------------------------------------------------------------------------
// Launch
// ---------------------------------------------------------------------------
extern "C" void kernel_launch(void* const* d_in, const int* in_sizes, int n_in,
                              void* d_out, int out_size)
{
    const float* x    = (const float*)d_in[0];
    const float* y    = (const float*)d_in[1];
    const float* wqkv = (const float*)d_in[2];
    const float* wl1  = (const float*)d_in[3];
    const float* g1   = (const float*)d_in[4];
    const float* b1   = (const float*)d_in[5];
    const float* m1   = (const float*)d_in[6];
    const float* v1   = (const float*)d_in[7];
    const float* wl2  = (const float*)d_in[8];
    const float* g2   = (const float*)d_in[9];
    const float* b2   = (const float*)d_in[10];
    const float* m2   = (const float*)d_in[11];
    const float* v2   = (const float*)d_in[12];
    const float* wdw  = (const float*)d_in[13];
    const float* gp   = (const float*)d_in[14];
    const float* bp   = (const float*)d_in[15];
    const float* mp   = (const float*)d_in[16];
    const float* vp   = (const float*)d_in[17];
    const float* wpw  = (const float*)d_in[18];
    const float* rpb  = (const float*)d_in[19];
    float* out = (float*)d_out;

    prep_kernel<<<1, 256>>>(g1, b1, m1, v1, g2, b2, m2, v2, gp, bp, mp, vp);
    cvt_wqkv<<<768, 256>>>(wqkv);
    cvt_wpw<<<256, 256>>>(wpw);
    cvt_wlocal<<<2560, 256>>>(wl1, wl2);
    cvt_x<<<32768, 256>>>(x);
    cvt_y<<<32768, 256>>>(y);

    // local branch (K=2560, 1-pass fp16, aligned shifted-y loads) -> g_lh
    gemm_local_f16<<<dim3(2, 1024), 256>>>();

    // qkv (M=768, K=256, 1-pass fp16) -> g_qkvh (fp16, window-major)
    gemm_aligned<<<dim3(6, 1024), 256>>>(nullptr, 768, 256, 0);

    // tensor-core attention (4 window-heads per block) -> g_attnh (fp16)
    attn_mma<<<dim3(512, 16), 128>>>(rpb);

    // fused pools + depthwise conv + BN -> g_dwh (fp16)
    dwpool_kernel<<<dim3(64, 512), 256>>>(wdw);

    // pointwise (M=256, K=256, 1-pass fp16) -> out
    gemm_aligned<<<dim3(2, 1024), 256>>>(out, 256, 256, 1);
}

// round 15
// speedup vs baseline: 1.1961x; 1.1961x over previous
#include <cuda_runtime.h>
#include <cuda_fp16.h>
#include <math.h>
#include <stdint.h>

// ---------------------------------------------------------------------------
// Problem constants: B=2, C=256, H=W=256, SSM=256, NH=16, HD=16, WS=8
// ---------------------------------------------------------------------------
#define PPLANE 65536
#define NBATCH 2

typedef unsigned long long u64;
typedef unsigned short u16;

__device__ u16 g_lh   [NBATCH * 256 * PPLANE];     // local branch out (fp16)
__device__ u16 g_qkvh [NBATCH * 768 * PPLANE];     // fp16, window-major pixels
__device__ u16 g_attnh[NBATCH * 256 * PPLANE];     // fp16 attention output

// pre-converted fp16 operands
__device__ u16 g_xh [NBATCH * 256 * PPLANE];
__device__ u16 g_yh [NBATCH * 256 * PPLANE];
__device__ u16 g_dwh[NBATCH * 256 * PPLANE];
__device__ u16 g_wqh [768 * 256];
__device__ u16 g_wph [256 * 256];
__device__ u16 g_wlh [256 * 2560];

__device__ float g_inv1[256], g_inv2[256], g_biasc[256], g_invp[256], g_biasp[256];

// ---------------------------------------------------------------------------
// helpers
// ---------------------------------------------------------------------------
__device__ __forceinline__ uint32_t smem_u32(const void* p) {
    uint32_t a;
    asm("{ .reg .u64 t; cvta.to.shared.u64 t, %1; cvt.u32.u64 %0, t; }"
        : "=r"(a) : "l"(p));
    return a;
}
__device__ __forceinline__ u16 h16(float v) {
    __half h = __float2half_rn(v);
    return *reinterpret_cast<u16*>(&h);
}
__device__ __forceinline__ float f16f(u16 v) {
    __half h = *reinterpret_cast<__half*>(&v);
    return __half2float(h);
}
__device__ __forceinline__ uint32_t h2bits(float a, float b) {
    __half2 h = __floats2half2_rn(a, b);
    return *reinterpret_cast<uint32_t*>(&h);
}
__device__ __forceinline__ void ldsm4(uint32_t* r, uint32_t a) {
    asm volatile("ldmatrix.sync.aligned.m8n8.x4.shared.b16 {%0,%1,%2,%3},[%4];"
                 : "=r"(r[0]), "=r"(r[1]), "=r"(r[2]), "=r"(r[3]) : "r"(a));
}
__device__ __forceinline__ void ldsm4t(uint32_t* r, uint32_t a) {
    asm volatile("ldmatrix.sync.aligned.m8n8.x4.trans.shared.b16 {%0,%1,%2,%3},[%4];"
                 : "=r"(r[0]), "=r"(r[1]), "=r"(r[2]), "=r"(r[3]) : "r"(a));
}
__device__ __forceinline__ void mma16(float* c, const uint32_t* a, const uint32_t* b) {
    asm volatile(
        "mma.sync.aligned.m16n8k16.row.col.f32.f16.f16.f32 "
        "{%0,%1,%2,%3},{%4,%5,%6,%7},{%8,%9},{%0,%1,%2,%3};"
        : "+f"(c[0]), "+f"(c[1]), "+f"(c[2]), "+f"(c[3])
        : "r"(a[0]), "r"(a[1]), "r"(a[2]), "r"(a[3]), "r"(b[0]), "r"(b[1]));
}

#define ASTRIDE 48
#define BSTRIDE 272
#define ABYTES (128 * ASTRIDE)
#define BBYTES (16 * BSTRIDE)

__device__ __forceinline__ int perm_px(int p) {
    int h = p >> 8, w = p & 255;
    return (((h >> 3) * 32 + (w >> 3)) << 6) + ((h & 7) << 3) + (w & 7);
}

// ---------------------------------------------------------------------------
// Prep kernels
// ---------------------------------------------------------------------------
__global__ void prep_kernel(const float* __restrict__ g1, const float* __restrict__ b1,
                            const float* __restrict__ m1, const float* __restrict__ v1,
                            const float* __restrict__ g2, const float* __restrict__ b2,
                            const float* __restrict__ m2, const float* __restrict__ v2,
                            const float* __restrict__ gp, const float* __restrict__ bp,
                            const float* __restrict__ mp, const float* __restrict__ vp)
{
    int c = threadIdx.x;
    float i1 = g1[c] * rsqrtf(v1[c] + 1e-5f);
    float i2 = g2[c] * rsqrtf(v2[c] + 1e-5f);
    g_inv1[c] = i1;
    g_inv2[c] = i2;
    g_biasc[c] = (b1[c] - m1[c] * i1) + (b2[c] - m2[c] * i2);
    float ip = gp[c] * rsqrtf(vp[c] + 1e-5f);
    g_invp[c] = ip;
    g_biasp[c] = bp[c] - mp[c] * ip;
}

__global__ void cvt_wqkv(const float* __restrict__ w)
{
    int i = blockIdx.x * 256 + threadIdx.x;
    if (i >= 768 * 256) return;
    float sc = (i < 256 * 256) ? 0.25f : 1.0f;
    g_wqh[i] = h16(w[i] * sc);
}
__global__ void cvt_wpw(const float* __restrict__ w)
{
    int i = blockIdx.x * 256 + threadIdx.x;
    g_wph[i] = h16(w[i]);
}
__global__ void cvt_wlocal(const float* __restrict__ w1, const float* __restrict__ w2)
{
    int i = blockIdx.x * 256 + threadIdx.x;
    if (i >= 256 * 2560) return;
    int m = i / 2560, k = i - m * 2560;
    float v = (k < 2304) ? w1[m * 2304 + k] * g_inv1[m]
                         : w2[m * 256 + (k - 2304)] * g_inv2[m];
    g_wlh[i] = h16(v);
}
__global__ void cvt_x(const float* __restrict__ x)
{
    size_t base = ((size_t)blockIdx.x * 256 + threadIdx.x) * 4;
    float4 v = *(const float4*)(x + base);
    u16 h[4] = { h16(v.x), h16(v.y), h16(v.z), h16(v.w) };
    *(uint2*)(g_xh + base) = *(uint2*)h;
}
__global__ void cvt_y(const float* __restrict__ y)
{
    size_t base = ((size_t)blockIdx.x * 256 + threadIdx.x) * 4;
    float4 v = *(const float4*)(y + base);
    u16 h[4] = { h16(v.x), h16(v.y), h16(v.z), h16(v.w) };
    *(uint2*)(g_yh + base) = *(uint2*)h;
}

// ---------------------------------------------------------------------------
// Consumer: one K=16 step, 1-pass fp16.
// ---------------------------------------------------------------------------
__device__ __forceinline__ void mma_step(
    uint32_t sAh, uint32_t sB,
    int wm, int wn, int lane, float acc[4][4][4])
{
    int t  = lane >> 3;
    int r8 = lane & 7;
    uint32_t bh[4][2];
#pragma unroll
    for (int ng = 0; ng < 2; ++ng) {
        uint32_t addr = ((t >> 1) * 8 + r8) * BSTRIDE + (wn + ng * 16 + (t & 1) * 8) * 2;
        uint32_t tb[4];
        ldsm4t(tb, sB + addr);
        bh[ng * 2 + 0][0] = tb[0]; bh[ng * 2 + 0][1] = tb[2];
        bh[ng * 2 + 1][0] = tb[1]; bh[ng * 2 + 1][1] = tb[3];
    }
    uint32_t abase = ((t & 1) * 8 + r8) * ASTRIDE + (t >> 1) * 16;
#pragma unroll
    for (int mt = 0; mt < 4; ++mt) {
        uint32_t arow = abase + (wm + mt * 16) * ASTRIDE;
        uint32_t ah[4];
        ldsm4(ah, sAh + arow);
#pragma unroll
        for (int j = 0; j < 4; ++j) mma16(acc[mt][j], ah, bh[j]);
    }
}

// ---------------------------------------------------------------------------
// Aligned GEMM, 1-pass fp16, operands device-side.
//   which==0: A = wqkv (M=768,K=256), B = x,  C = g_qkvh (fp16, permuted)
//   which==1: A = wpw  (M=256,K=256), B = dw, C = extC (fp32)
// grid = (M/128, 1024)
// ---------------------------------------------------------------------------
__global__ __launch_bounds__(256, 2) void gemm_aligned(float* extC, int M, int K, int which)
{
    __shared__ __align__(16) char AhS[2][ABYTES];
    __shared__ __align__(16) char BS [2][BBYTES];

    const u16 *Ah_g, *B_g;
    if (which == 0) { Ah_g = g_wqh; B_g = g_xh; }
    else            { Ah_g = g_wph; B_g = g_dwh; }

    int tid = threadIdx.x;
    int m0  = blockIdx.x * 128;
    int pg0 = blockIdx.y * 128;
    int b   = pg0 >> 16;
    int p0  = pg0 & 65535;
    int lane = tid & 31, warp = tid >> 5;
    int wm = (warp >> 2) * 64, wn = (warp & 3) * 32;

    int am = tid >> 1, ak = (tid & 1) * 8;
    const u16* Abh = Ah_g + (size_t)(m0 + am) * K + ak;
    int bk = tid >> 4, bn = (tid & 15) * 8;
    size_t bbase = ((size_t)(b * K + bk) << 16) + p0 + bn;

    int aoff = am * ASTRIDE + ak * 2;
    int boff = bk * BSTRIDE + bn * 2;

    float acc[4][4][4];
#pragma unroll
    for (int i = 0; i < 4; ++i)
#pragma unroll
        for (int j = 0; j < 4; ++j)
#pragma unroll
            for (int r = 0; r < 4; ++r) acc[i][j][r] = 0.f;

    uint4 rah, rb;
    auto gload = [&](int k0) {
        rah = *(const uint4*)(Abh + k0);
        rb  = *(const uint4*)(B_g + bbase + ((size_t)k0 << 16));
    };
    auto sstore = [&](int s) {
        *(uint4*)(AhS[s] + aoff) = rah;
        *(uint4*)(BS[s]  + boff) = rb;
    };

    int nch = K >> 4;
    gload(0);
    sstore(0);
    if (nch > 1) gload(16);
    __syncthreads();

    for (int ch = 0; ch < nch; ++ch) {
        if (ch + 1 < nch) sstore((ch + 1) & 1);
        if (ch + 2 < nch) gload((ch + 2) << 4);
        int s = ch & 1;
        mma_step(smem_u32(AhS[s]), smem_u32(BS[s]), wm, wn, lane, acc);
        __syncthreads();
    }

    int g = lane >> 2, tig = lane & 3;
#pragma unroll
    for (int mt = 0; mt < 4; ++mt) {
        int r0 = m0 + wm + mt * 16 + g;
#pragma unroll
        for (int j = 0; j < 4; ++j) {
            int col = p0 + wn + j * 8 + tig * 2;
            if (which == 0) {
                int pc = perm_px(col);
                size_t i0 = ((size_t)(b * M + r0) << 16) + pc;
                size_t i1 = ((size_t)(b * M + r0 + 8) << 16) + pc;
                *(uint32_t*)&g_qkvh[i0] = h2bits(acc[mt][j][0], acc[mt][j][1]);
                *(uint32_t*)&g_qkvh[i1] = h2bits(acc[mt][j][2], acc[mt][j][3]);
            } else {
                size_t i0 = ((size_t)(b * M + r0) << 16) + col;
                size_t i1 = ((size_t)(b * M + r0 + 8) << 16) + col;
                *(float2*)&extC[i0] = make_float2(acc[mt][j][0], acc[mt][j][1]);
                *(float2*)&extC[i1] = make_float2(acc[mt][j][2], acc[mt][j][3]);
            }
        }
    }
}

// ---------------------------------------------------------------------------
// Fused local branch GEMM (1-pass fp16), K=2560, B gathered from g_yh.
// grid = (2, 1024).  Output fp16 (+bias) -> g_lh.
// ---------------------------------------------------------------------------
__global__ __launch_bounds__(256, 2) void gemm_local_f16(void)
{
    __shared__ __align__(16) char AhS[2][ABYTES];
    __shared__ __align__(16) char BS [2][BBYTES];

    int tid = threadIdx.x;
    int m0  = blockIdx.x * 128;
    int pg0 = blockIdx.y * 128;
    int b   = pg0 >> 16;
    int p0  = pg0 & 65535;
    int h   = p0 >> 8;
    int w0  = p0 & 255;
    int lane = tid & 31, warp = tid >> 5;
    int wm = (warp >> 2) * 64, wn = (warp & 3) * 32;

    int am = tid >> 1, ak = (tid & 1) * 8;
    int mg = m0 + am;
    int bk = tid >> 4, bn = (tid & 15) * 8;

    int aoff = am * ASTRIDE + ak * 2;
    int boff = bk * BSTRIDE + bn * 2;

    const u16* Abh = g_wlh + (size_t)mg * 2560 + ak;

    float acc[4][4][4];
#pragma unroll
    for (int i = 0; i < 4; ++i)
#pragma unroll
        for (int j = 0; j < 4; ++j)
#pragma unroll
            for (int r = 0; r < 4; ++r) acc[i][j][r] = 0.f;

    uint4 rah, rb;
    auto gload = [&](int k0) {
        rah = *(const uint4*)(Abh + k0);
        int k = k0 + bk;
        int ci, dy, dx;
        if (k < 2304) {
            ci = k / 9;
            int tap = k - ci * 9;
            int r = tap / 3;
            dy = r - 1;
            dx = tap - r * 3 - 1;
        } else { ci = k - 2304; dy = 0; dx = 0; }
        int hh = h + dy;
        bool hok = (hh >= 0) && (hh < 256);
        const u16* row = g_yh + ((size_t)(b * 256 + ci) << 16) + hh * 256;
        uint32_t v[8];
#pragma unroll
        for (int j = 0; j < 8; ++j) {
            int ww = w0 + bn + j + dx;
            v[j] = (hok && ww >= 0 && ww < 256) ? (uint32_t)row[ww] : 0u;
        }
        uint32_t* pb = (uint32_t*)&rb;
#pragma unroll
        for (int j = 0; j < 4; ++j) pb[j] = v[2 * j] | (v[2 * j + 1] << 16);
    };
    auto sstore = [&](int s) {
        *(uint4*)(AhS[s] + aoff) = rah;
        *(uint4*)(BS[s]  + boff) = rb;
    };

    const int nch = 160;
    gload(0);
    sstore(0);
    gload(16);
    __syncthreads();

    for (int ch = 0; ch < nch; ++ch) {
        if (ch + 1 < nch) sstore((ch + 1) & 1);
        if (ch + 2 < nch) gload((ch + 2) << 4);
        int s = ch & 1;
        mma_step(smem_u32(AhS[s]), smem_u32(BS[s]), wm, wn, lane, acc);
        __syncthreads();
    }

    int g = lane >> 2, tig = lane & 3;
#pragma unroll
    for (int mt = 0; mt < 4; ++mt) {
        int r0 = m0 + wm + mt * 16 + g;
        float bi0 = g_biasc[r0];
        float bi1 = g_biasc[r0 + 8];
#pragma unroll
        for (int j = 0; j < 4; ++j) {
            int col = p0 + wn + j * 8 + tig * 2;
            size_t i0 = ((size_t)(b * 256 + r0) << 16) + col;
            size_t i1 = ((size_t)(b * 256 + r0 + 8) << 16) + col;
            *(uint32_t*)&g_lh[i0] = h2bits(acc[mt][j][0] + bi0, acc[mt][j][1] + bi0);
            *(uint32_t*)&g_lh[i1] = h2bits(acc[mt][j][2] + bi1, acc[mt][j][3] + bi1);
        }
    }
}

// ---------------------------------------------------------------------------
// Tensor-core windowed attention: 1 warp = 1 (window, head). fp16 output.
// ---------------------------------------------------------------------------
#define QSTR 72

__global__ __launch_bounds__(128) void attn_mma(const float* __restrict__ rpb)
{
    __shared__ u16 qkvS[4][48][QSTR];
    __shared__ float rpbs[225];

    int tid  = threadIdx.x;
    int warp = tid >> 5, lane = tid & 31;
    int head = blockIdx.y;
    int win  = blockIdx.x * 4 + warp;
    int b    = win >> 10;
    int wloc = win & 1023;

    for (int t = tid; t < 225; t += 128) rpbs[t] = rpb[t * 16 + head];

    {
        int ppb = wloc * 64;
        for (int f = lane; f < 768; f += 32) {
            int row = f >> 4;
            int c4  = (f & 15) * 4;
            int ch  = b * 768 + head * 16 + (row & 15) + (row >> 4) * 256;
            uint2 v = *(const uint2*)(g_qkvh + (((size_t)ch) << 16) + ppb + c4);
            *(uint2*)&qkvS[warp][row][c4] = v;
        }
    }
    __syncthreads();

    uint32_t sQ = smem_u32(&qkvS[warp][0][0]);
    uint32_t sK = smem_u32(&qkvS[warp][16][0]);
    uint32_t sV = smem_u32(&qkvS[warp][32][0]);

    int t = lane >> 3, r8 = lane & 7;
    int g = lane >> 2, tig = lane & 3;

    uint32_t bqk[8][2];
#pragma unroll
    for (int ng = 0; ng < 4; ++ng) {
        uint32_t addr = sK + (((t >> 1) * 8 + r8) * QSTR + ng * 16 + (t & 1) * 8) * 2;
        uint32_t tb[4];
        ldsm4t(tb, addr);
        bqk[2 * ng + 0][0] = tb[0]; bqk[2 * ng + 0][1] = tb[2];
        bqk[2 * ng + 1][0] = tb[1]; bqk[2 * ng + 1][1] = tb[3];
    }
    uint32_t bv[4][2][2];
#pragma unroll
    for (int kt = 0; kt < 4; ++kt) {
        uint32_t addr = sV + (((t & 1) * 8 + r8) * QSTR + kt * 16 + (t >> 1) * 8) * 2;
        uint32_t tb[4];
        ldsm4(tb, addr);
        bv[kt][0][0] = tb[0]; bv[kt][0][1] = tb[2];
        bv[kt][1][0] = tb[1]; bv[kt][1][1] = tb[3];
    }

    int wy = wloc >> 5, wx = wloc & 31;

#pragma unroll
    for (int mt = 0; mt < 4; ++mt) {
        uint32_t aQ[4];
        ldsm4t(aQ, sQ + (((t >> 1) * 8 + r8) * QSTR + mt * 16 + (t & 1) * 8) * 2);

        float s[8][4];
#pragma unroll
        for (int nt = 0; nt < 8; ++nt) {
            s[nt][0] = s[nt][1] = s[nt][2] = s[nt][3] = 0.f;
            mma16(s[nt], aQ, bqk[nt]);
        }

        int row0 = mt * 16 + g, row1 = row0 + 8;
        int yi0 = row0 >> 3, xi0 = row0 & 7;
        int yi1 = row1 >> 3, xi1 = row1 & 7;
        float mx0 = -1e30f, mx1 = -1e30f;
#pragma unroll
        for (int nt = 0; nt < 8; ++nt) {
            int col = nt * 8 + tig * 2;
            int yj = col >> 3, xj = col & 7;
            s[nt][0] += rpbs[(yi0 - yj + 7) * 15 + (xi0 - xj + 7)];
            s[nt][1] += rpbs[(yi0 - yj + 7) * 15 + (xi0 - xj + 6)];
            s[nt][2] += rpbs[(yi1 - yj + 7) * 15 + (xi1 - xj + 7)];
            s[nt][3] += rpbs[(yi1 - yj + 7) * 15 + (xi1 - xj + 6)];
            mx0 = fmaxf(mx0, fmaxf(s[nt][0], s[nt][1]));
            mx1 = fmaxf(mx1, fmaxf(s[nt][2], s[nt][3]));
        }
        mx0 = fmaxf(mx0, __shfl_xor_sync(0xffffffffu, mx0, 1));
        mx0 = fmaxf(mx0, __shfl_xor_sync(0xffffffffu, mx0, 2));
        mx1 = fmaxf(mx1, __shfl_xor_sync(0xffffffffu, mx1, 1));
        mx1 = fmaxf(mx1, __shfl_xor_sync(0xffffffffu, mx1, 2));

        float sum0 = 0.f, sum1 = 0.f;
#pragma unroll
        for (int nt = 0; nt < 8; ++nt) {
            s[nt][0] = __expf(s[nt][0] - mx0);
            s[nt][1] = __expf(s[nt][1] - mx0);
            s[nt][2] = __expf(s[nt][2] - mx1);
            s[nt][3] = __expf(s[nt][3] - mx1);
            sum0 += s[nt][0] + s[nt][1];
            sum1 += s[nt][2] + s[nt][3];
        }
        sum0 += __shfl_xor_sync(0xffffffffu, sum0, 1);
        sum0 += __shfl_xor_sync(0xffffffffu, sum0, 2);
        sum1 += __shfl_xor_sync(0xffffffffu, sum1, 1);
        sum1 += __shfl_xor_sync(0xffffffffu, sum1, 2);
        float inv0 = 1.f / sum0, inv1 = 1.f / sum1;

        float o[2][4];
        o[0][0]=o[0][1]=o[0][2]=o[0][3]=0.f;
        o[1][0]=o[1][1]=o[1][2]=o[1][3]=0.f;
#pragma unroll
        for (int kt = 0; kt < 4; ++kt) {
            uint32_t aP[4];
            aP[0] = h2bits(s[2 * kt][0],     s[2 * kt][1]);
            aP[1] = h2bits(s[2 * kt][2],     s[2 * kt][3]);
            aP[2] = h2bits(s[2 * kt + 1][0], s[2 * kt + 1][1]);
            aP[3] = h2bits(s[2 * kt + 1][2], s[2 * kt + 1][3]);
            mma16(o[0], aP, bv[kt][0]);
            mma16(o[1], aP, bv[kt][1]);
        }

        int p0 = ((wy * 8 + yi0) << 8) + wx * 8 + xi0;
        int p1 = ((wy * 8 + yi1) << 8) + wx * 8 + xi1;
#pragma unroll
        for (int nd = 0; nd < 2; ++nd) {
            int ch0 = b * 256 + head * 16 + nd * 8 + tig * 2;
            g_attnh[(((size_t)ch0)     << 16) + p0] = h16(o[nd][0] * inv0);
            g_attnh[(((size_t)ch0 + 1) << 16) + p0] = h16(o[nd][1] * inv0);
            g_attnh[(((size_t)ch0)     << 16) + p1] = h16(o[nd][2] * inv1);
            g_attnh[(((size_t)ch0 + 1) << 16) + p1] = h16(o[nd][3] * inv1);
        }
    }
}

// ---------------------------------------------------------------------------
// Fused pool + depthwise 8x8 conv + BN -> single fp16 output g_dwh.
// ---------------------------------------------------------------------------
__global__ __launch_bounds__(256) void dwpool_kernel(const float* __restrict__ w_dw)
{
    __shared__ float attnS[46][48];
    __shared__ float midS[39][40];
    __shared__ float ws[64];

    int tix = blockIdx.x;
    int bc  = blockIdx.y;
    int c   = bc & 255;
    int ty0 = (tix >> 3) * 32;
    int tx0 = (tix & 7) * 32;
    int tid = threadIdx.x;

    const u16* aplane = g_attnh + ((size_t)bc << 16);
    const u16* lplane = g_lh    + ((size_t)bc << 16);

    for (int idx = tid; idx < 46 * 46; idx += 256) {
        int r  = idx / 46;
        int cc = idx - r * 46;
        int gh = ty0 - 6 + r;
        int gw = tx0 - 6 + cc;
        float v = 0.f;
        if (gh >= 0 && gh < 256 && gw >= 0 && gw < 256) v = f16f(aplane[gh * 256 + gw]);
        attnS[r][cc] = v;
    }
    if (tid < 64) ws[tid] = w_dw[c * 64 + tid];
    __syncthreads();

    for (int idx = tid; idx < 39 * 39; idx += 256) {
        int r  = idx / 39;
        int cc = idx - r * 39;
        int gh = ty0 - 3 + r;
        int gw = tx0 - 3 + cc;
        float v = 0.f;
        if (gh >= 0 && gh <= 256 && gw >= 0 && gw <= 256) {
            int gh2 = (gh == 256) ? 254 : gh;
            int gw2 = (gw == 256) ? 254 : gw;
            int co = gw2 - (tx0 - 6);
            float vs = 0.f;
#pragma unroll
            for (int tt2 = gh2 - 3; tt2 <= gh2 + 4; ++tt2) {
                if (tt2 >= 0 && tt2 <= 256) {
                    int tt = (tt2 == 256) ? 254 : tt2;
                    vs += attnS[tt - (ty0 - 6)][co];
                }
            }
            int ro = gh2 - (ty0 - 6);
            float hs = 0.f;
#pragma unroll
            for (int ss2 = gw2 - 3; ss2 <= gw2 + 4; ++ss2) {
                if (ss2 >= 0 && ss2 <= 256) {
                    int ss = (ss2 == 256) ? 254 : ss2;
                    hs += attnS[ro][ss - (tx0 - 6)];
                }
            }
            v = (vs + hs) * 0.125f + f16f(lplane[gh2 * 256 + gw2]);
        }
        midS[r][cc] = v;
    }
    __syncthreads();

    int lw  = tid & 31;
    int lh0 = (tid >> 5) * 4;
    float acc[4] = {0.f, 0.f, 0.f, 0.f};
#pragma unroll
    for (int j = 0; j < 8; ++j) {
        float wcol[8];
#pragma unroll
        for (int i = 0; i < 8; ++i) wcol[i] = ws[i * 8 + j];
#pragma unroll
        for (int r = 0; r < 11; ++r) {
            float v = midS[lh0 + r][lw + j];
#pragma unroll
            for (int a = 0; a < 4; ++a) {
                int i = r - a;
                if (i >= 0 && i < 8) acc[a] += v * wcol[i];
            }
        }
    }
    float ip = g_invp[c];
    float bb = g_biasp[c];
#pragma unroll
    for (int a = 0; a < 4; ++a) {
        int h = ty0 + lh0 + a;
        float r = acc[a] * ip + bb;
        size_t idx = ((size_t)bc << 16) + h * 256 + tx0 + lw;
        g_dwh[idx] = h16(r);
    }
}

// ---------------------------------------------------------------------------
// Launch
// ---------------------------------------------------------------------------
extern "C" void kernel_launch(void* const* d_in, const int* in_sizes, int n_in,
                              void* d_out, int out_size)
{
    const float* x    = (const float*)d_in[0];
    const float* y    = (const float*)d_in[1];
    const float* wqkv = (const float*)d_in[2];
    const float* wl1  = (const float*)d_in[3];
    const float* g1   = (const float*)d_in[4];
    const float* b1   = (const float*)d_in[5];
    const float* m1   = (const float*)d_in[6];
    const float* v1   = (const float*)d_in[7];
    const float* wl2  = (const float*)d_in[8];
    const float* g2   = (const float*)d_in[9];
    const float* b2   = (const float*)d_in[10];
    const float* m2   = (const float*)d_in[11];
    const float* v2   = (const float*)d_in[12];
    const float* wdw  = (const float*)d_in[13];
    const float* gp   = (const float*)d_in[14];
    const float* bp   = (const float*)d_in[15];
    const float* mp   = (const float*)d_in[16];
    const float* vp   = (const float*)d_in[17];
    const float* wpw  = (const float*)d_in[18];
    const float* rpb  = (const float*)d_in[19];
    float* out = (float*)d_out;

    prep_kernel<<<1, 256>>>(g1, b1, m1, v1, g2, b2, m2, v2, gp, bp, mp, vp);
    cvt_wqkv<<<768, 256>>>(wqkv);
    cvt_wpw<<<256, 256>>>(wpw);
    cvt_wlocal<<<2560, 256>>>(wl1, wl2);
    cvt_x<<<32768, 256>>>(x);
    cvt_y<<<32768, 256>>>(y);

    // local branch (K=2560, 1-pass fp16) -> g_lh (fp16)
    gemm_local_f16<<<dim3(2, 1024), 256>>>();

    // qkv (M=768, K=256, 1-pass fp16) -> g_qkvh (fp16, window-major)
    gemm_aligned<<<dim3(6, 1024), 256>>>(nullptr, 768, 256, 0);

    // tensor-core attention (4 window-heads per block) -> g_attnh (fp16)
    attn_mma<<<dim3(512, 16), 128>>>(rpb);

    // fused pools + depthwise conv + BN -> g_dwh (fp16)
    dwpool_kernel<<<dim3(64, 512), 256>>>(wdw);

    // pointwise (M=256, K=256, 1-pass fp16) -> out
    gemm_aligned<<<dim3(2, 1024), 256>>>(out, 256, 256, 1);
}

// round 16
// speedup vs baseline: 1.2650x; 1.0576x over previous
#include <cuda_runtime.h>
#include <cuda_fp16.h>
#include <math.h>
#include <stdint.h>

// ---------------------------------------------------------------------------
// Problem constants: B=2, C=256, H=W=256, SSM=256, NH=16, HD=16, WS=8
// ---------------------------------------------------------------------------
#define PPLANE 65536
#define NBATCH 2

typedef unsigned long long u64;
typedef unsigned short u16;

__device__ u16 g_lh   [NBATCH * 256 * PPLANE];     // local branch out (fp16)
__device__ u16 g_qkvh [NBATCH * 768 * PPLANE];     // fp16, window-major pixels
__device__ u16 g_attnh[NBATCH * 256 * PPLANE];     // fp16 attention output

// pre-converted fp16 operands
__device__ u16 g_xh [NBATCH * 256 * PPLANE];
__device__ u16 g_yh [NBATCH * 256 * PPLANE];
__device__ u16 g_dwh[NBATCH * 256 * PPLANE];
__device__ u16 g_wqh [768 * 256];
__device__ u16 g_wph [256 * 256];
__device__ u16 g_wlh [256 * 2560];

__device__ float g_inv1[256], g_inv2[256], g_biasc[256], g_invp[256], g_biasp[256];

// ---------------------------------------------------------------------------
// helpers
// ---------------------------------------------------------------------------
__device__ __forceinline__ uint32_t smem_u32(const void* p) {
    uint32_t a;
    asm("{ .reg .u64 t; cvta.to.shared.u64 t, %1; cvt.u32.u64 %0, t; }"
        : "=r"(a) : "l"(p));
    return a;
}
__device__ __forceinline__ u16 h16(float v) {
    __half h = __float2half_rn(v);
    return *reinterpret_cast<u16*>(&h);
}
__device__ __forceinline__ float f16f(u16 v) {
    __half h = *reinterpret_cast<__half*>(&v);
    return __half2float(h);
}
__device__ __forceinline__ uint32_t h2bits(float a, float b) {
    __half2 h = __floats2half2_rn(a, b);
    return *reinterpret_cast<uint32_t*>(&h);
}
__device__ __forceinline__ void ldsm4(uint32_t* r, uint32_t a) {
    asm volatile("ldmatrix.sync.aligned.m8n8.x4.shared.b16 {%0,%1,%2,%3},[%4];"
                 : "=r"(r[0]), "=r"(r[1]), "=r"(r[2]), "=r"(r[3]) : "r"(a));
}
__device__ __forceinline__ void ldsm4t(uint32_t* r, uint32_t a) {
    asm volatile("ldmatrix.sync.aligned.m8n8.x4.trans.shared.b16 {%0,%1,%2,%3},[%4];"
                 : "=r"(r[0]), "=r"(r[1]), "=r"(r[2]), "=r"(r[3]) : "r"(a));
}
__device__ __forceinline__ void mma16(float* c, const uint32_t* a, const uint32_t* b) {
    asm volatile(
        "mma.sync.aligned.m16n8k16.row.col.f32.f16.f16.f32 "
        "{%0,%1,%2,%3},{%4,%5,%6,%7},{%8,%9},{%0,%1,%2,%3};"
        : "+f"(c[0]), "+f"(c[1]), "+f"(c[2]), "+f"(c[3])
        : "r"(a[0]), "r"(a[1]), "r"(a[2]), "r"(a[3]), "r"(b[0]), "r"(b[1]));
}

#define ASTRIDE 48
#define BSTRIDE 272
#define ABYTES (128 * ASTRIDE)
#define BBYTES (16 * BSTRIDE)

__device__ __forceinline__ int perm_px(int p) {
    int h = p >> 8, w = p & 255;
    return (((h >> 3) * 32 + (w >> 3)) << 6) + ((h & 7) << 3) + (w & 7);
}

// ---------------------------------------------------------------------------
// Prep kernels
// ---------------------------------------------------------------------------
__global__ void prep_kernel(const float* __restrict__ g1, const float* __restrict__ b1,
                            const float* __restrict__ m1, const float* __restrict__ v1,
                            const float* __restrict__ g2, const float* __restrict__ b2,
                            const float* __restrict__ m2, const float* __restrict__ v2,
                            const float* __restrict__ gp, const float* __restrict__ bp,
                            const float* __restrict__ mp, const float* __restrict__ vp)
{
    int c = threadIdx.x;
    float i1 = g1[c] * rsqrtf(v1[c] + 1e-5f);
    float i2 = g2[c] * rsqrtf(v2[c] + 1e-5f);
    g_inv1[c] = i1;
    g_inv2[c] = i2;
    g_biasc[c] = (b1[c] - m1[c] * i1) + (b2[c] - m2[c] * i2);
    float ip = gp[c] * rsqrtf(vp[c] + 1e-5f);
    g_invp[c] = ip;
    g_biasp[c] = bp[c] - mp[c] * ip;
}

// all weights in one kernel: [0,196608) wqkv | [196608,262144) wpw | rest wlocal
__global__ void cvt_weights(const float* __restrict__ wq, const float* __restrict__ wp,
                            const float* __restrict__ w1, const float* __restrict__ w2)
{
    int i = blockIdx.x * 256 + threadIdx.x;
    if (i < 196608) {
        float sc = (i < 65536) ? 0.25f : 1.0f;
        g_wqh[i] = h16(wq[i] * sc);
    } else if (i < 262144) {
        int j = i - 196608;
        g_wph[j] = h16(wp[j]);
    } else {
        int j = i - 262144;
        if (j >= 256 * 2560) return;
        int m = j / 2560, k = j - m * 2560;
        float v = (k < 2304) ? w1[m * 2304 + k] * g_inv1[m]
                             : w2[m * 256 + (k - 2304)] * g_inv2[m];
        g_wlh[j] = h16(v);
    }
}
// x and y in one kernel (blockIdx.y: 0 = x, 1 = y)
__global__ void cvt_xy(const float* __restrict__ x, const float* __restrict__ y)
{
    size_t base = ((size_t)blockIdx.x * 256 + threadIdx.x) * 4;
    const float* src = blockIdx.y ? y : x;
    u16* dst = blockIdx.y ? g_yh : g_xh;
    float4 v = *(const float4*)(src + base);
    u16 h[4] = { h16(v.x), h16(v.y), h16(v.z), h16(v.w) };
    *(uint2*)(dst + base) = *(uint2*)h;
}

// ---------------------------------------------------------------------------
// Consumer: one K=16 step, 1-pass fp16.
// ---------------------------------------------------------------------------
__device__ __forceinline__ void mma_step(
    uint32_t sAh, uint32_t sB,
    int wm, int wn, int lane, float acc[4][4][4])
{
    int t  = lane >> 3;
    int r8 = lane & 7;
    uint32_t bh[4][2];
#pragma unroll
    for (int ng = 0; ng < 2; ++ng) {
        uint32_t addr = ((t >> 1) * 8 + r8) * BSTRIDE + (wn + ng * 16 + (t & 1) * 8) * 2;
        uint32_t tb[4];
        ldsm4t(tb, sB + addr);
        bh[ng * 2 + 0][0] = tb[0]; bh[ng * 2 + 0][1] = tb[2];
        bh[ng * 2 + 1][0] = tb[1]; bh[ng * 2 + 1][1] = tb[3];
    }
    uint32_t abase = ((t & 1) * 8 + r8) * ASTRIDE + (t >> 1) * 16;
#pragma unroll
    for (int mt = 0; mt < 4; ++mt) {
        uint32_t arow = abase + (wm + mt * 16) * ASTRIDE;
        uint32_t ah[4];
        ldsm4(ah, sAh + arow);
#pragma unroll
        for (int j = 0; j < 4; ++j) mma16(acc[mt][j], ah, bh[j]);
    }
}

// ---------------------------------------------------------------------------
// Aligned GEMM, 1-pass fp16, operands device-side.
//   which==0: A = wqkv (M=768,K=256), B = x,  C = g_qkvh (fp16, permuted)
//   which==1: A = wpw  (M=256,K=256), B = dw, C = extC (fp32)
// grid = (M/128, 1024)
// ---------------------------------------------------------------------------
__global__ __launch_bounds__(256, 2) void gemm_aligned(float* extC, int M, int K, int which)
{
    __shared__ __align__(16) char AhS[2][ABYTES];
    __shared__ __align__(16) char BS [2][BBYTES];

    const u16 *Ah_g, *B_g;
    if (which == 0) { Ah_g = g_wqh; B_g = g_xh; }
    else            { Ah_g = g_wph; B_g = g_dwh; }

    int tid = threadIdx.x;
    int m0  = blockIdx.x * 128;
    int pg0 = blockIdx.y * 128;
    int b   = pg0 >> 16;
    int p0  = pg0 & 65535;
    int lane = tid & 31, warp = tid >> 5;
    int wm = (warp >> 2) * 64, wn = (warp & 3) * 32;

    int am = tid >> 1, ak = (tid & 1) * 8;
    const u16* Abh = Ah_g + (size_t)(m0 + am) * K + ak;
    int bk = tid >> 4, bn = (tid & 15) * 8;
    size_t bbase = ((size_t)(b * K + bk) << 16) + p0 + bn;

    int aoff = am * ASTRIDE + ak * 2;
    int boff = bk * BSTRIDE + bn * 2;

    float acc[4][4][4];
#pragma unroll
    for (int i = 0; i < 4; ++i)
#pragma unroll
        for (int j = 0; j < 4; ++j)
#pragma unroll
            for (int r = 0; r < 4; ++r) acc[i][j][r] = 0.f;

    uint4 rah, rb;
    auto gload = [&](int k0) {
        rah = *(const uint4*)(Abh + k0);
        rb  = *(const uint4*)(B_g + bbase + ((size_t)k0 << 16));
    };
    auto sstore = [&](int s) {
        *(uint4*)(AhS[s] + aoff) = rah;
        *(uint4*)(BS[s]  + boff) = rb;
    };

    int nch = K >> 4;
    gload(0);
    sstore(0);
    if (nch > 1) gload(16);
    __syncthreads();

    for (int ch = 0; ch < nch; ++ch) {
        if (ch + 1 < nch) sstore((ch + 1) & 1);
        if (ch + 2 < nch) gload((ch + 2) << 4);
        int s = ch & 1;
        mma_step(smem_u32(AhS[s]), smem_u32(BS[s]), wm, wn, lane, acc);
        __syncthreads();
    }

    int g = lane >> 2, tig = lane & 3;
#pragma unroll
    for (int mt = 0; mt < 4; ++mt) {
        int r0 = m0 + wm + mt * 16 + g;
#pragma unroll
        for (int j = 0; j < 4; ++j) {
            int col = p0 + wn + j * 8 + tig * 2;
            if (which == 0) {
                int pc = perm_px(col);
                size_t i0 = ((size_t)(b * M + r0) << 16) + pc;
                size_t i1 = ((size_t)(b * M + r0 + 8) << 16) + pc;
                *(uint32_t*)&g_qkvh[i0] = h2bits(acc[mt][j][0], acc[mt][j][1]);
                *(uint32_t*)&g_qkvh[i1] = h2bits(acc[mt][j][2], acc[mt][j][3]);
            } else {
                size_t i0 = ((size_t)(b * M + r0) << 16) + col;
                size_t i1 = ((size_t)(b * M + r0 + 8) << 16) + col;
                *(float2*)&extC[i0] = make_float2(acc[mt][j][0], acc[mt][j][1]);
                *(float2*)&extC[i1] = make_float2(acc[mt][j][2], acc[mt][j][3]);
            }
        }
    }
}

// ---------------------------------------------------------------------------
// Fused local branch GEMM (1-pass fp16), K=2560, B gathered from g_yh.
// grid = (2, 1024).  Output fp16 (+bias) -> g_lh.
// ---------------------------------------------------------------------------
__global__ __launch_bounds__(256, 2) void gemm_local_f16(void)
{
    __shared__ __align__(16) char AhS[2][ABYTES];
    __shared__ __align__(16) char BS [2][BBYTES];

    int tid = threadIdx.x;
    int m0  = blockIdx.x * 128;
    int pg0 = blockIdx.y * 128;
    int b   = pg0 >> 16;
    int p0  = pg0 & 65535;
    int h   = p0 >> 8;
    int w0  = p0 & 255;
    int lane = tid & 31, warp = tid >> 5;
    int wm = (warp >> 2) * 64, wn = (warp & 3) * 32;

    int am = tid >> 1, ak = (tid & 1) * 8;
    int mg = m0 + am;
    int bk = tid >> 4, bn = (tid & 15) * 8;

    int aoff = am * ASTRIDE + ak * 2;
    int boff = bk * BSTRIDE + bn * 2;

    const u16* Abh = g_wlh + (size_t)mg * 2560 + ak;

    float acc[4][4][4];
#pragma unroll
    for (int i = 0; i < 4; ++i)
#pragma unroll
        for (int j = 0; j < 4; ++j)
#pragma unroll
            for (int r = 0; r < 4; ++r) acc[i][j][r] = 0.f;

    uint4 rah, rb;
    auto gload = [&](int k0) {
        rah = *(const uint4*)(Abh + k0);
        int k = k0 + bk;
        int ci, dy, dx;
        if (k < 2304) {
            ci = k / 9;
            int tap = k - ci * 9;
            int r = tap / 3;
            dy = r - 1;
            dx = tap - r * 3 - 1;
        } else { ci = k - 2304; dy = 0; dx = 0; }
        int hh = h + dy;
        bool hok = (hh >= 0) && (hh < 256);
        const u16* row = g_yh + ((size_t)(b * 256 + ci) << 16) + hh * 256;
        uint32_t v[8];
#pragma unroll
        for (int j = 0; j < 8; ++j) {
            int ww = w0 + bn + j + dx;
            v[j] = (hok && ww >= 0 && ww < 256) ? (uint32_t)row[ww] : 0u;
        }
        uint32_t* pb = (uint32_t*)&rb;
#pragma unroll
        for (int j = 0; j < 4; ++j) pb[j] = v[2 * j] | (v[2 * j + 1] << 16);
    };
    auto sstore = [&](int s) {
        *(uint4*)(AhS[s] + aoff) = rah;
        *(uint4*)(BS[s]  + boff) = rb;
    };

    const int nch = 160;
    gload(0);
    sstore(0);
    gload(16);
    __syncthreads();

    for (int ch = 0; ch < nch; ++ch) {
        if (ch + 1 < nch) sstore((ch + 1) & 1);
        if (ch + 2 < nch) gload((ch + 2) << 4);
        int s = ch & 1;
        mma_step(smem_u32(AhS[s]), smem_u32(BS[s]), wm, wn, lane, acc);
        __syncthreads();
    }

    int g = lane >> 2, tig = lane & 3;
#pragma unroll
    for (int mt = 0; mt < 4; ++mt) {
        int r0 = m0 + wm + mt * 16 + g;
        float bi0 = g_biasc[r0];
        float bi1 = g_biasc[r0 + 8];
#pragma unroll
        for (int j = 0; j < 4; ++j) {
            int col = p0 + wn + j * 8 + tig * 2;
            size_t i0 = ((size_t)(b * 256 + r0) << 16) + col;
            size_t i1 = ((size_t)(b * 256 + r0 + 8) << 16) + col;
            *(uint32_t*)&g_lh[i0] = h2bits(acc[mt][j][0] + bi0, acc[mt][j][1] + bi0);
            *(uint32_t*)&g_lh[i1] = h2bits(acc[mt][j][2] + bi1, acc[mt][j][3] + bi1);
        }
    }
}

// ---------------------------------------------------------------------------
// Tensor-core windowed attention: 1 warp = 1 (window, head). fp16 output.
// ---------------------------------------------------------------------------
#define QSTR 72

__global__ __launch_bounds__(128) void attn_mma(const float* __restrict__ rpb)
{
    __shared__ u16 qkvS[4][48][QSTR];
    __shared__ float rpbs[225];

    int tid  = threadIdx.x;
    int warp = tid >> 5, lane = tid & 31;
    int head = blockIdx.y;
    int win  = blockIdx.x * 4 + warp;
    int b    = win >> 10;
    int wloc = win & 1023;

    for (int t = tid; t < 225; t += 128) rpbs[t] = rpb[t * 16 + head];

    {
        int ppb = wloc * 64;
        for (int f = lane; f < 768; f += 32) {
            int row = f >> 4;
            int c4  = (f & 15) * 4;
            int ch  = b * 768 + head * 16 + (row & 15) + (row >> 4) * 256;
            uint2 v = *(const uint2*)(g_qkvh + (((size_t)ch) << 16) + ppb + c4);
            *(uint2*)&qkvS[warp][row][c4] = v;
        }
    }
    __syncthreads();

    uint32_t sQ = smem_u32(&qkvS[warp][0][0]);
    uint32_t sK = smem_u32(&qkvS[warp][16][0]);
    uint32_t sV = smem_u32(&qkvS[warp][32][0]);

    int t = lane >> 3, r8 = lane & 7;
    int g = lane >> 2, tig = lane & 3;

    uint32_t bqk[8][2];
#pragma unroll
    for (int ng = 0; ng < 4; ++ng) {
        uint32_t addr = sK + (((t >> 1) * 8 + r8) * QSTR + ng * 16 + (t & 1) * 8) * 2;
        uint32_t tb[4];
        ldsm4t(tb, addr);
        bqk[2 * ng + 0][0] = tb[0]; bqk[2 * ng + 0][1] = tb[2];
        bqk[2 * ng + 1][0] = tb[1]; bqk[2 * ng + 1][1] = tb[3];
    }
    uint32_t bv[4][2][2];
#pragma unroll
    for (int kt = 0; kt < 4; ++kt) {
        uint32_t addr = sV + (((t & 1) * 8 + r8) * QSTR + kt * 16 + (t >> 1) * 8) * 2;
        uint32_t tb[4];
        ldsm4(tb, addr);
        bv[kt][0][0] = tb[0]; bv[kt][0][1] = tb[2];
        bv[kt][1][0] = tb[1]; bv[kt][1][1] = tb[3];
    }

    int wy = wloc >> 5, wx = wloc & 31;

#pragma unroll
    for (int mt = 0; mt < 4; ++mt) {
        uint32_t aQ[4];
        ldsm4t(aQ, sQ + (((t >> 1) * 8 + r8) * QSTR + mt * 16 + (t & 1) * 8) * 2);

        float s[8][4];
#pragma unroll
        for (int nt = 0; nt < 8; ++nt) {
            s[nt][0] = s[nt][1] = s[nt][2] = s[nt][3] = 0.f;
            mma16(s[nt], aQ, bqk[nt]);
        }

        int row0 = mt * 16 + g, row1 = row0 + 8;
        int yi0 = row0 >> 3, xi0 = row0 & 7;
        int yi1 = row1 >> 3, xi1 = row1 & 7;
        float mx0 = -1e30f, mx1 = -1e30f;
#pragma unroll
        for (int nt = 0; nt < 8; ++nt) {
            int col = nt * 8 + tig * 2;
            int yj = col >> 3, xj = col & 7;
            s[nt][0] += rpbs[(yi0 - yj + 7) * 15 + (xi0 - xj + 7)];
            s[nt][1] += rpbs[(yi0 - yj + 7) * 15 + (xi0 - xj + 6)];
            s[nt][2] += rpbs[(yi1 - yj + 7) * 15 + (xi1 - xj + 7)];
            s[nt][3] += rpbs[(yi1 - yj + 7) * 15 + (xi1 - xj + 6)];
            mx0 = fmaxf(mx0, fmaxf(s[nt][0], s[nt][1]));
            mx1 = fmaxf(mx1, fmaxf(s[nt][2], s[nt][3]));
        }
        mx0 = fmaxf(mx0, __shfl_xor_sync(0xffffffffu, mx0, 1));
        mx0 = fmaxf(mx0, __shfl_xor_sync(0xffffffffu, mx0, 2));
        mx1 = fmaxf(mx1, __shfl_xor_sync(0xffffffffu, mx1, 1));
        mx1 = fmaxf(mx1, __shfl_xor_sync(0xffffffffu, mx1, 2));

        float sum0 = 0.f, sum1 = 0.f;
#pragma unroll
        for (int nt = 0; nt < 8; ++nt) {
            s[nt][0] = __expf(s[nt][0] - mx0);
            s[nt][1] = __expf(s[nt][1] - mx0);
            s[nt][2] = __expf(s[nt][2] - mx1);
            s[nt][3] = __expf(s[nt][3] - mx1);
            sum0 += s[nt][0] + s[nt][1];
            sum1 += s[nt][2] + s[nt][3];
        }
        sum0 += __shfl_xor_sync(0xffffffffu, sum0, 1);
        sum0 += __shfl_xor_sync(0xffffffffu, sum0, 2);
        sum1 += __shfl_xor_sync(0xffffffffu, sum1, 1);
        sum1 += __shfl_xor_sync(0xffffffffu, sum1, 2);
        float inv0 = 1.f / sum0, inv1 = 1.f / sum1;

        float o[2][4];
        o[0][0]=o[0][1]=o[0][2]=o[0][3]=0.f;
        o[1][0]=o[1][1]=o[1][2]=o[1][3]=0.f;
#pragma unroll
        for (int kt = 0; kt < 4; ++kt) {
            uint32_t aP[4];
            aP[0] = h2bits(s[2 * kt][0],     s[2 * kt][1]);
            aP[1] = h2bits(s[2 * kt][2],     s[2 * kt][3]);
            aP[2] = h2bits(s[2 * kt + 1][0], s[2 * kt + 1][1]);
            aP[3] = h2bits(s[2 * kt + 1][2], s[2 * kt + 1][3]);
            mma16(o[0], aP, bv[kt][0]);
            mma16(o[1], aP, bv[kt][1]);
        }

        int p0 = ((wy * 8 + yi0) << 8) + wx * 8 + xi0;
        int p1 = ((wy * 8 + yi1) << 8) + wx * 8 + xi1;
#pragma unroll
        for (int nd = 0; nd < 2; ++nd) {
            int ch0 = b * 256 + head * 16 + nd * 8 + tig * 2;
            g_attnh[(((size_t)ch0)     << 16) + p0] = h16(o[nd][0] * inv0);
            g_attnh[(((size_t)ch0 + 1) << 16) + p0] = h16(o[nd][1] * inv0);
            g_attnh[(((size_t)ch0)     << 16) + p1] = h16(o[nd][2] * inv1);
            g_attnh[(((size_t)ch0 + 1) << 16) + p1] = h16(o[nd][3] * inv1);
        }
    }
}

// ---------------------------------------------------------------------------
// Fused pool + depthwise 8x8 conv + BN -> single fp16 output g_dwh.
// Pool loops de-branched: attnS is zero-padded, only t==256 needs the
// reflect-to-254 correction (index 256 itself holds 0).
// ---------------------------------------------------------------------------
__global__ __launch_bounds__(256) void dwpool_kernel(const float* __restrict__ w_dw)
{
    __shared__ float attnS[46][48];
    __shared__ float midS[39][40];
    __shared__ float ws[64];

    int tix = blockIdx.x;
    int bc  = blockIdx.y;
    int c   = bc & 255;
    int ty0 = (tix >> 3) * 32;
    int tx0 = (tix & 7) * 32;
    int tid = threadIdx.x;

    const u16* aplane = g_attnh + ((size_t)bc << 16);
    const u16* lplane = g_lh    + ((size_t)bc << 16);

    for (int idx = tid; idx < 46 * 46; idx += 256) {
        int r  = idx / 46;
        int cc = idx - r * 46;
        int gh = ty0 - 6 + r;
        int gw = tx0 - 6 + cc;
        float v = 0.f;
        if (gh >= 0 && gh < 256 && gw >= 0 && gw < 256) v = f16f(aplane[gh * 256 + gw]);
        attnS[r][cc] = v;
    }
    if (tid < 64) ws[tid] = w_dw[c * 64 + tid];
    __syncthreads();

    for (int idx = tid; idx < 39 * 39; idx += 256) {
        int r  = idx / 39;
        int cc = idx - r * 39;
        int gh = ty0 - 3 + r;
        int gw = tx0 - 3 + cc;
        float v = 0.f;
        if (gh >= 0 && gh <= 256 && gw >= 0 && gw <= 256) {
            int gh2 = (gh == 256) ? 254 : gh;
            int gw2 = (gw == 256) ? 254 : gw;
            int co = gw2 - (tx0 - 6);
            int rbase = gh2 - 3 - (ty0 - 6);      // local row of first tap
            float vs = 0.f;
#pragma unroll
            for (int q = 0; q < 8; ++q) vs += attnS[rbase + q][co];
            if (gh2 >= 252) vs += attnS[254 - (ty0 - 6)][co];

            int ro = gh2 - (ty0 - 6);
            int cbase = gw2 - 3 - (tx0 - 6);
            float hs = 0.f;
#pragma unroll
            for (int q = 0; q < 8; ++q) hs += attnS[ro][cbase + q];
            if (gw2 >= 252) hs += attnS[ro][254 - (tx0 - 6)];

            v = (vs + hs) * 0.125f + f16f(lplane[gh2 * 256 + gw2]);
        }
        midS[r][cc] = v;
    }
    __syncthreads();

    int lw  = tid & 31;
    int lh0 = (tid >> 5) * 4;
    float acc[4] = {0.f, 0.f, 0.f, 0.f};
#pragma unroll
    for (int j = 0; j < 8; ++j) {
        float wcol[8];
#pragma unroll
        for (int i = 0; i < 8; ++i) wcol[i] = ws[i * 8 + j];
#pragma unroll
        for (int r = 0; r < 11; ++r) {
            float v = midS[lh0 + r][lw + j];
#pragma unroll
            for (int a = 0; a < 4; ++a) {
                int i = r - a;
                if (i >= 0 && i < 8) acc[a] += v * wcol[i];
            }
        }
    }
    float ip = g_invp[c];
    float bb = g_biasp[c];
#pragma unroll
    for (int a = 0; a < 4; ++a) {
        int h = ty0 + lh0 + a;
        float r = acc[a] * ip + bb;
        size_t idx = ((size_t)bc << 16) + h * 256 + tx0 + lw;
        g_dwh[idx] = h16(r);
    }
}

// ---------------------------------------------------------------------------
// Launch
// ---------------------------------------------------------------------------
extern "C" void kernel_launch(void* const* d_in, const int* in_sizes, int n_in,
                              void* d_out, int out_size)
{
    const float* x    = (const float*)d_in[0];
    const float* y    = (const float*)d_in[1];
    const float* wqkv = (const float*)d_in[2];
    const float* wl1  = (const float*)d_in[3];
    const float* g1   = (const float*)d_in[4];
    const float* b1   = (const float*)d_in[5];
    const float* m1   = (const float*)d_in[6];
    const float* v1   = (const float*)d_in[7];
    const float* wl2  = (const float*)d_in[8];
    const float* g2   = (const float*)d_in[9];
    const float* b2   = (const float*)d_in[10];
    const float* m2   = (const float*)d_in[11];
    const float* v2   = (const float*)d_in[12];
    const float* wdw  = (const float*)d_in[13];
    const float* gp   = (const float*)d_in[14];
    const float* bp   = (const float*)d_in[15];
    const float* mp   = (const float*)d_in[16];
    const float* vp   = (const float*)d_in[17];
    const float* wpw  = (const float*)d_in[18];
    const float* rpb  = (const float*)d_in[19];
    float* out = (float*)d_out;

    prep_kernel<<<1, 256>>>(g1, b1, m1, v1, g2, b2, m2, v2, gp, bp, mp, vp);
    cvt_weights<<<3584, 256>>>(wqkv, wpw, wl1, wl2);
    cvt_xy<<<dim3(32768, 2), 256>>>(x, y);

    // local branch (K=2560, 1-pass fp16) -> g_lh (fp16)
    gemm_local_f16<<<dim3(2, 1024), 256>>>();

    // qkv (M=768, K=256, 1-pass fp16) -> g_qkvh (fp16, window-major)
    gemm_aligned<<<dim3(6, 1024), 256>>>(nullptr, 768, 256, 0);

    // tensor-core attention (4 window-heads per block) -> g_attnh (fp16)
    attn_mma<<<dim3(512, 16), 128>>>(rpb);

    // fused pools + depthwise conv + BN -> g_dwh (fp16)
    dwpool_kernel<<<dim3(64, 512), 256>>>(wdw);

    // pointwise (M=256, K=256, 1-pass fp16) -> out
    gemm_aligned<<<dim3(2, 1024), 256>>>(out, 256, 256, 1);
}

// round 17
// speedup vs baseline: 1.3482x; 1.0657x over previous
#include <cuda_runtime.h>
#include <cuda_fp16.h>
#include <math.h>
#include <stdint.h>

// ---------------------------------------------------------------------------
// Problem constants: B=2, C=256, H=W=256, SSM=256, NH=16, HD=16, WS=8
// ---------------------------------------------------------------------------
#define PPLANE 65536
#define NBATCH 2

// padded y plane: 258 rows x 272 cols, data at [row+1][col+8]; halo stays 0
#define YROWS 258
#define YCOLS 272
#define YPLANE (YROWS * YCOLS)

typedef unsigned long long u64;
typedef unsigned short u16;

__device__ u16 g_lh   [NBATCH * 256 * PPLANE];     // local branch out (fp16)
__device__ u16 g_qkvh [NBATCH * 768 * PPLANE];     // fp16, window-major pixels
__device__ u16 g_attnh[NBATCH * 256 * PPLANE];     // fp16 attention output

// pre-converted fp16 operands
__device__ u16 g_xh [NBATCH * 256 * PPLANE];
__device__ u16 g_yp [NBATCH * 256 * YPLANE];       // zero-halo padded y
__device__ u16 g_dwh[NBATCH * 256 * PPLANE];
__device__ u16 g_wqh [768 * 256];
__device__ u16 g_wph [256 * 256];
__device__ u16 g_wlh [256 * 2560];

__device__ float g_inv1[256], g_inv2[256], g_biasc[256], g_invp[256], g_biasp[256];

// ---------------------------------------------------------------------------
// helpers
// ---------------------------------------------------------------------------
__device__ __forceinline__ uint32_t smem_u32(const void* p) {
    uint32_t a;
    asm("{ .reg .u64 t; cvta.to.shared.u64 t, %1; cvt.u32.u64 %0, t; }"
        : "=r"(a) : "l"(p));
    return a;
}
__device__ __forceinline__ u16 h16(float v) {
    __half h = __float2half_rn(v);
    return *reinterpret_cast<u16*>(&h);
}
__device__ __forceinline__ float f16f(u16 v) {
    __half h = *reinterpret_cast<__half*>(&v);
    return __half2float(h);
}
__device__ __forceinline__ uint32_t h2bits(float a, float b) {
    __half2 h = __floats2half2_rn(a, b);
    return *reinterpret_cast<uint32_t*>(&h);
}
__device__ __forceinline__ void ldsm4(uint32_t* r, uint32_t a) {
    asm volatile("ldmatrix.sync.aligned.m8n8.x4.shared.b16 {%0,%1,%2,%3},[%4];"
                 : "=r"(r[0]), "=r"(r[1]), "=r"(r[2]), "=r"(r[3]) : "r"(a));
}
__device__ __forceinline__ void ldsm4t(uint32_t* r, uint32_t a) {
    asm volatile("ldmatrix.sync.aligned.m8n8.x4.trans.shared.b16 {%0,%1,%2,%3},[%4];"
                 : "=r"(r[0]), "=r"(r[1]), "=r"(r[2]), "=r"(r[3]) : "r"(a));
}
__device__ __forceinline__ void mma16(float* c, const uint32_t* a, const uint32_t* b) {
    asm volatile(
        "mma.sync.aligned.m16n8k16.row.col.f32.f16.f16.f32 "
        "{%0,%1,%2,%3},{%4,%5,%6,%7},{%8,%9},{%0,%1,%2,%3};"
        : "+f"(c[0]), "+f"(c[1]), "+f"(c[2]), "+f"(c[3])
        : "r"(a[0]), "r"(a[1]), "r"(a[2]), "r"(a[3]), "r"(b[0]), "r"(b[1]));
}

#define ASTRIDE 48
#define BSTRIDE 272
#define ABYTES (128 * ASTRIDE)
#define BBYTES (16 * BSTRIDE)

__device__ __forceinline__ int perm_px(int p) {
    int h = p >> 8, w = p & 255;
    return (((h >> 3) * 32 + (w >> 3)) << 6) + ((h & 7) << 3) + (w & 7);
}

// ---------------------------------------------------------------------------
// Prep kernels
// ---------------------------------------------------------------------------
__global__ void prep_kernel(const float* __restrict__ g1, const float* __restrict__ b1,
                            const float* __restrict__ m1, const float* __restrict__ v1,
                            const float* __restrict__ g2, const float* __restrict__ b2,
                            const float* __restrict__ m2, const float* __restrict__ v2,
                            const float* __restrict__ gp, const float* __restrict__ bp,
                            const float* __restrict__ mp, const float* __restrict__ vp)
{
    int c = threadIdx.x;
    float i1 = g1[c] * rsqrtf(v1[c] + 1e-5f);
    float i2 = g2[c] * rsqrtf(v2[c] + 1e-5f);
    g_inv1[c] = i1;
    g_inv2[c] = i2;
    g_biasc[c] = (b1[c] - m1[c] * i1) + (b2[c] - m2[c] * i2);
    float ip = gp[c] * rsqrtf(vp[c] + 1e-5f);
    g_invp[c] = ip;
    g_biasp[c] = bp[c] - mp[c] * ip;
}

// all weights in one kernel: [0,196608) wqkv | [196608,262144) wpw | rest wlocal
__global__ void cvt_weights(const float* __restrict__ wq, const float* __restrict__ wp,
                            const float* __restrict__ w1, const float* __restrict__ w2)
{
    int i = blockIdx.x * 256 + threadIdx.x;
    if (i < 196608) {
        float sc = (i < 65536) ? 0.25f : 1.0f;
        g_wqh[i] = h16(wq[i] * sc);
    } else if (i < 262144) {
        int j = i - 196608;
        g_wph[j] = h16(wp[j]);
    } else {
        int j = i - 262144;
        if (j >= 256 * 2560) return;
        int m = j / 2560, k = j - m * 2560;
        float v = (k < 2304) ? w1[m * 2304 + k] * g_inv1[m]
                             : w2[m * 256 + (k - 2304)] * g_inv2[m];
        g_wlh[j] = h16(v);
    }
}
// x (plain layout) and y (zero-halo padded layout) in one kernel
__global__ void cvt_xy(const float* __restrict__ x, const float* __restrict__ y)
{
    size_t base = ((size_t)blockIdx.x * 256 + threadIdx.x) * 4;
    if (blockIdx.y == 0) {
        float4 v = *(const float4*)(x + base);
        u16 h[4] = { h16(v.x), h16(v.y), h16(v.z), h16(v.w) };
        *(uint2*)(g_xh + base) = *(uint2*)h;
    } else {
        float4 v = *(const float4*)(y + base);
        u16 h[4] = { h16(v.x), h16(v.y), h16(v.z), h16(v.w) };
        size_t plane = base >> 16;
        int rem = (int)(base & 65535);
        int hh = rem >> 8, ww = rem & 255;
        *(uint2*)(g_yp + plane * YPLANE + (hh + 1) * YCOLS + 8 + ww) = *(uint2*)h;
    }
}

// ---------------------------------------------------------------------------
// Consumer: one K=16 step, 1-pass fp16.
// ---------------------------------------------------------------------------
__device__ __forceinline__ void mma_step(
    uint32_t sAh, uint32_t sB,
    int wm, int wn, int lane, float acc[4][4][4])
{
    int t  = lane >> 3;
    int r8 = lane & 7;
    uint32_t bh[4][2];
#pragma unroll
    for (int ng = 0; ng < 2; ++ng) {
        uint32_t addr = ((t >> 1) * 8 + r8) * BSTRIDE + (wn + ng * 16 + (t & 1) * 8) * 2;
        uint32_t tb[4];
        ldsm4t(tb, sB + addr);
        bh[ng * 2 + 0][0] = tb[0]; bh[ng * 2 + 0][1] = tb[2];
        bh[ng * 2 + 1][0] = tb[1]; bh[ng * 2 + 1][1] = tb[3];
    }
    uint32_t abase = ((t & 1) * 8 + r8) * ASTRIDE + (t >> 1) * 16;
#pragma unroll
    for (int mt = 0; mt < 4; ++mt) {
        uint32_t arow = abase + (wm + mt * 16) * ASTRIDE;
        uint32_t ah[4];
        ldsm4(ah, sAh + arow);
#pragma unroll
        for (int j = 0; j < 4; ++j) mma16(acc[mt][j], ah, bh[j]);
    }
}

// ---------------------------------------------------------------------------
// Aligned GEMM, 1-pass fp16, operands device-side.
//   which==0: A = wqkv (M=768,K=256), B = x,  C = g_qkvh (fp16, permuted)
//   which==1: A = wpw  (M=256,K=256), B = dw, C = extC (fp32)
// grid = (M/128, 1024)
// ---------------------------------------------------------------------------
__global__ __launch_bounds__(256, 2) void gemm_aligned(float* extC, int M, int K, int which)
{
    __shared__ __align__(16) char AhS[2][ABYTES];
    __shared__ __align__(16) char BS [2][BBYTES];

    const u16 *Ah_g, *B_g;
    if (which == 0) { Ah_g = g_wqh; B_g = g_xh; }
    else            { Ah_g = g_wph; B_g = g_dwh; }

    int tid = threadIdx.x;
    int m0  = blockIdx.x * 128;
    int pg0 = blockIdx.y * 128;
    int b   = pg0 >> 16;
    int p0  = pg0 & 65535;
    int lane = tid & 31, warp = tid >> 5;
    int wm = (warp >> 2) * 64, wn = (warp & 3) * 32;

    int am = tid >> 1, ak = (tid & 1) * 8;
    const u16* Abh = Ah_g + (size_t)(m0 + am) * K + ak;
    int bk = tid >> 4, bn = (tid & 15) * 8;
    size_t bbase = ((size_t)(b * K + bk) << 16) + p0 + bn;

    int aoff = am * ASTRIDE + ak * 2;
    int boff = bk * BSTRIDE + bn * 2;

    float acc[4][4][4];
#pragma unroll
    for (int i = 0; i < 4; ++i)
#pragma unroll
        for (int j = 0; j < 4; ++j)
#pragma unroll
            for (int r = 0; r < 4; ++r) acc[i][j][r] = 0.f;

    uint4 rah, rb;
    auto gload = [&](int k0) {
        rah = *(const uint4*)(Abh + k0);
        rb  = *(const uint4*)(B_g + bbase + ((size_t)k0 << 16));
    };
    auto sstore = [&](int s) {
        *(uint4*)(AhS[s] + aoff) = rah;
        *(uint4*)(BS[s]  + boff) = rb;
    };

    int nch = K >> 4;
    gload(0);
    sstore(0);
    if (nch > 1) gload(16);
    __syncthreads();

    for (int ch = 0; ch < nch; ++ch) {
        if (ch + 1 < nch) sstore((ch + 1) & 1);
        if (ch + 2 < nch) gload((ch + 2) << 4);
        int s = ch & 1;
        mma_step(smem_u32(AhS[s]), smem_u32(BS[s]), wm, wn, lane, acc);
        __syncthreads();
    }

    int g = lane >> 2, tig = lane & 3;
#pragma unroll
    for (int mt = 0; mt < 4; ++mt) {
        int r0 = m0 + wm + mt * 16 + g;
#pragma unroll
        for (int j = 0; j < 4; ++j) {
            int col = p0 + wn + j * 8 + tig * 2;
            if (which == 0) {
                int pc = perm_px(col);
                size_t i0 = ((size_t)(b * M + r0) << 16) + pc;
                size_t i1 = ((size_t)(b * M + r0 + 8) << 16) + pc;
                *(uint32_t*)&g_qkvh[i0] = h2bits(acc[mt][j][0], acc[mt][j][1]);
                *(uint32_t*)&g_qkvh[i1] = h2bits(acc[mt][j][2], acc[mt][j][3]);
            } else {
                size_t i0 = ((size_t)(b * M + r0) << 16) + col;
                size_t i1 = ((size_t)(b * M + r0 + 8) << 16) + col;
                *(float2*)&extC[i0] = make_float2(acc[mt][j][0], acc[mt][j][1]);
                *(float2*)&extC[i1] = make_float2(acc[mt][j][2], acc[mt][j][3]);
            }
        }
    }
}

// ---------------------------------------------------------------------------
// Fused local branch GEMM (1-pass fp16), K=2560.
// B gathered from the zero-halo padded y: 1 aligned uint4 + 1 edge u16 per
// chunk, byte_perm realignment, no bounds predicates.
// grid = (2, 1024).  Output fp16 (+bias) -> g_lh.
// ---------------------------------------------------------------------------
__global__ __launch_bounds__(256, 2) void gemm_local_f16(void)
{
    __shared__ __align__(16) char AhS[2][ABYTES];
    __shared__ __align__(16) char BS [2][BBYTES];

    int tid = threadIdx.x;
    int m0  = blockIdx.x * 128;
    int pg0 = blockIdx.y * 128;
    int b   = pg0 >> 16;
    int p0  = pg0 & 65535;
    int h   = p0 >> 8;
    int w0  = p0 & 255;
    int lane = tid & 31, warp = tid >> 5;
    int wm = (warp >> 2) * 64, wn = (warp & 3) * 32;

    int am = tid >> 1, ak = (tid & 1) * 8;
    int mg = m0 + am;
    int bk = tid >> 4, bn = (tid & 15) * 8;

    int aoff = am * ASTRIDE + ak * 2;
    int boff = bk * BSTRIDE + bn * 2;

    const u16* Abh = g_wlh + (size_t)mg * 2560 + ak;
    // base of this block's pixel run in the padded plane (row h+1, col 8+w0+bn)
    const u16* Ybase = g_yp + ((size_t)b * 256) * YPLANE + (h + 1) * YCOLS + 8 + w0 + bn;

    float acc[4][4][4];
#pragma unroll
    for (int i = 0; i < 4; ++i)
#pragma unroll
        for (int j = 0; j < 4; ++j)
#pragma unroll
            for (int r = 0; r < 4; ++r) acc[i][j][r] = 0.f;

    uint4 rah, rb;
    auto gload = [&](int k0) {
        rah = *(const uint4*)(Abh + k0);
        int k = k0 + bk;
        int ci, dy, dx;
        if (k < 2304) {
            ci = k / 9;
            int tap = k - ci * 9;
            int r = tap / 3;
            dy = r - 1;
            dx = tap - r * 3 - 1;
        } else { ci = k - 2304; dy = 0; dx = 0; }
        const u16* row = Ybase + (size_t)ci * YPLANE + dy * YCOLS;
        uint4 V = *(const uint4*)row;
        uint32_t ew = (uint32_t)row[(dx == 1) ? 8 : -1];
        uint32_t m0p = __byte_perm(V.x, V.y, 0x5432);   // [p1,p2]
        uint32_t m1p = __byte_perm(V.y, V.z, 0x5432);   // [p3,p4]
        uint32_t m2p = __byte_perm(V.z, V.w, 0x5432);   // [p5,p6]
        uint32_t* pb = (uint32_t*)&rb;
        if (dx == 0) {
            pb[0] = V.x; pb[1] = V.y; pb[2] = V.z; pb[3] = V.w;
        } else if (dx < 0) {
            pb[0] = __byte_perm(V.x, ew, 0x1054);       // [e,p0]
            pb[1] = m0p; pb[2] = m1p; pb[3] = m2p;
        } else {
            pb[0] = m0p; pb[1] = m1p; pb[2] = m2p;
            pb[3] = __byte_perm(V.w, ew, 0x5432);       // [p7,e]
        }
    };
    auto sstore = [&](int s) {
        *(uint4*)(AhS[s] + aoff) = rah;
        *(uint4*)(BS[s]  + boff) = rb;
    };

    const int nch = 160;
    gload(0);
    sstore(0);
    gload(16);
    __syncthreads();

    for (int ch = 0; ch < nch; ++ch) {
        if (ch + 1 < nch) sstore((ch + 1) & 1);
        if (ch + 2 < nch) gload((ch + 2) << 4);
        int s = ch & 1;
        mma_step(smem_u32(AhS[s]), smem_u32(BS[s]), wm, wn, lane, acc);
        __syncthreads();
    }

    int g = lane >> 2, tig = lane & 3;
#pragma unroll
    for (int mt = 0; mt < 4; ++mt) {
        int r0 = m0 + wm + mt * 16 + g;
        float bi0 = g_biasc[r0];
        float bi1 = g_biasc[r0 + 8];
#pragma unroll
        for (int j = 0; j < 4; ++j) {
            int col = p0 + wn + j * 8 + tig * 2;
            size_t i0 = ((size_t)(b * 256 + r0) << 16) + col;
            size_t i1 = ((size_t)(b * 256 + r0 + 8) << 16) + col;
            *(uint32_t*)&g_lh[i0] = h2bits(acc[mt][j][0] + bi0, acc[mt][j][1] + bi0);
            *(uint32_t*)&g_lh[i1] = h2bits(acc[mt][j][2] + bi1, acc[mt][j][3] + bi1);
        }
    }
}

// ---------------------------------------------------------------------------
// Tensor-core windowed attention: 1 warp = 1 (window, head). fp16 output.
// ---------------------------------------------------------------------------
#define QSTR 72

__global__ __launch_bounds__(128) void attn_mma(const float* __restrict__ rpb)
{
    __shared__ u16 qkvS[4][48][QSTR];
    __shared__ float rpbs[225];

    int tid  = threadIdx.x;
    int warp = tid >> 5, lane = tid & 31;
    int head = blockIdx.y;
    int win  = blockIdx.x * 4 + warp;
    int b    = win >> 10;
    int wloc = win & 1023;

    for (int t = tid; t < 225; t += 128) rpbs[t] = rpb[t * 16 + head];

    {
        int ppb = wloc * 64;
        for (int f = lane; f < 768; f += 32) {
            int row = f >> 4;
            int c4  = (f & 15) * 4;
            int ch  = b * 768 + head * 16 + (row & 15) + (row >> 4) * 256;
            uint2 v = *(const uint2*)(g_qkvh + (((size_t)ch) << 16) + ppb + c4);
            *(uint2*)&qkvS[warp][row][c4] = v;
        }
    }
    __syncthreads();

    uint32_t sQ = smem_u32(&qkvS[warp][0][0]);
    uint32_t sK = smem_u32(&qkvS[warp][16][0]);
    uint32_t sV = smem_u32(&qkvS[warp][32][0]);

    int t = lane >> 3, r8 = lane & 7;
    int g = lane >> 2, tig = lane & 3;

    uint32_t bqk[8][2];
#pragma unroll
    for (int ng = 0; ng < 4; ++ng) {
        uint32_t addr = sK + (((t >> 1) * 8 + r8) * QSTR + ng * 16 + (t & 1) * 8) * 2;
        uint32_t tb[4];
        ldsm4t(tb, addr);
        bqk[2 * ng + 0][0] = tb[0]; bqk[2 * ng + 0][1] = tb[2];
        bqk[2 * ng + 1][0] = tb[1]; bqk[2 * ng + 1][1] = tb[3];
    }
    uint32_t bv[4][2][2];
#pragma unroll
    for (int kt = 0; kt < 4; ++kt) {
        uint32_t addr = sV + (((t & 1) * 8 + r8) * QSTR + kt * 16 + (t >> 1) * 8) * 2;
        uint32_t tb[4];
        ldsm4(tb, addr);
        bv[kt][0][0] = tb[0]; bv[kt][0][1] = tb[2];
        bv[kt][1][0] = tb[1]; bv[kt][1][1] = tb[3];
    }

    int wy = wloc >> 5, wx = wloc & 31;

#pragma unroll
    for (int mt = 0; mt < 4; ++mt) {
        uint32_t aQ[4];
        ldsm4t(aQ, sQ + (((t >> 1) * 8 + r8) * QSTR + mt * 16 + (t & 1) * 8) * 2);

        float s[8][4];
#pragma unroll
        for (int nt = 0; nt < 8; ++nt) {
            s[nt][0] = s[nt][1] = s[nt][2] = s[nt][3] = 0.f;
            mma16(s[nt], aQ, bqk[nt]);
        }

        int row0 = mt * 16 + g, row1 = row0 + 8;
        int yi0 = row0 >> 3, xi0 = row0 & 7;
        int yi1 = row1 >> 3, xi1 = row1 & 7;
        float mx0 = -1e30f, mx1 = -1e30f;
#pragma unroll
        for (int nt = 0; nt < 8; ++nt) {
            int col = nt * 8 + tig * 2;
            int yj = col >> 3, xj = col & 7;
            s[nt][0] += rpbs[(yi0 - yj + 7) * 15 + (xi0 - xj + 7)];
            s[nt][1] += rpbs[(yi0 - yj + 7) * 15 + (xi0 - xj + 6)];
            s[nt][2] += rpbs[(yi1 - yj + 7) * 15 + (xi1 - xj + 7)];
            s[nt][3] += rpbs[(yi1 - yj + 7) * 15 + (xi1 - xj + 6)];
            mx0 = fmaxf(mx0, fmaxf(s[nt][0], s[nt][1]));
            mx1 = fmaxf(mx1, fmaxf(s[nt][2], s[nt][3]));
        }
        mx0 = fmaxf(mx0, __shfl_xor_sync(0xffffffffu, mx0, 1));
        mx0 = fmaxf(mx0, __shfl_xor_sync(0xffffffffu, mx0, 2));
        mx1 = fmaxf(mx1, __shfl_xor_sync(0xffffffffu, mx1, 1));
        mx1 = fmaxf(mx1, __shfl_xor_sync(0xffffffffu, mx1, 2));

        float sum0 = 0.f, sum1 = 0.f;
#pragma unroll
        for (int nt = 0; nt < 8; ++nt) {
            s[nt][0] = __expf(s[nt][0] - mx0);
            s[nt][1] = __expf(s[nt][1] - mx0);
            s[nt][2] = __expf(s[nt][2] - mx1);
            s[nt][3] = __expf(s[nt][3] - mx1);
            sum0 += s[nt][0] + s[nt][1];
            sum1 += s[nt][2] + s[nt][3];
        }
        sum0 += __shfl_xor_sync(0xffffffffu, sum0, 1);
        sum0 += __shfl_xor_sync(0xffffffffu, sum0, 2);
        sum1 += __shfl_xor_sync(0xffffffffu, sum1, 1);
        sum1 += __shfl_xor_sync(0xffffffffu, sum1, 2);
        float inv0 = 1.f / sum0, inv1 = 1.f / sum1;

        float o[2][4];
        o[0][0]=o[0][1]=o[0][2]=o[0][3]=0.f;
        o[1][0]=o[1][1]=o[1][2]=o[1][3]=0.f;
#pragma unroll
        for (int kt = 0; kt < 4; ++kt) {
            uint32_t aP[4];
            aP[0] = h2bits(s[2 * kt][0],     s[2 * kt][1]);
            aP[1] = h2bits(s[2 * kt][2],     s[2 * kt][3]);
            aP[2] = h2bits(s[2 * kt + 1][0], s[2 * kt + 1][1]);
            aP[3] = h2bits(s[2 * kt + 1][2], s[2 * kt + 1][3]);
            mma16(o[0], aP, bv[kt][0]);
            mma16(o[1], aP, bv[kt][1]);
        }

        int p0 = ((wy * 8 + yi0) << 8) + wx * 8 + xi0;
        int p1 = ((wy * 8 + yi1) << 8) + wx * 8 + xi1;
#pragma unroll
        for (int nd = 0; nd < 2; ++nd) {
            int ch0 = b * 256 + head * 16 + nd * 8 + tig * 2;
            g_attnh[(((size_t)ch0)     << 16) + p0] = h16(o[nd][0] * inv0);
            g_attnh[(((size_t)ch0 + 1) << 16) + p0] = h16(o[nd][1] * inv0);
            g_attnh[(((size_t)ch0)     << 16) + p1] = h16(o[nd][2] * inv1);
            g_attnh[(((size_t)ch0 + 1) << 16) + p1] = h16(o[nd][3] * inv1);
        }
    }
}

// ---------------------------------------------------------------------------
// Fused pool + depthwise 8x8 conv + BN -> single fp16 output g_dwh.
// Pool loops de-branched (attnS zero-padded; only reflect correction remains).
// ---------------------------------------------------------------------------
__global__ __launch_bounds__(256) void dwpool_kernel(const float* __restrict__ w_dw)
{
    __shared__ float attnS[46][48];
    __shared__ float midS[39][40];
    __shared__ float ws[64];

    int tix = blockIdx.x;
    int bc  = blockIdx.y;
    int c   = bc & 255;
    int ty0 = (tix >> 3) * 32;
    int tx0 = (tix & 7) * 32;
    int tid = threadIdx.x;

    const u16* aplane = g_attnh + ((size_t)bc << 16);
    const u16* lplane = g_lh    + ((size_t)bc << 16);

    for (int idx = tid; idx < 46 * 46; idx += 256) {
        int r  = idx / 46;
        int cc = idx - r * 46;
        int gh = ty0 - 6 + r;
        int gw = tx0 - 6 + cc;
        float v = 0.f;
        if (gh >= 0 && gh < 256 && gw >= 0 && gw < 256) v = f16f(aplane[gh * 256 + gw]);
        attnS[r][cc] = v;
    }
    if (tid < 64) ws[tid] = w_dw[c * 64 + tid];
    __syncthreads();

    for (int idx = tid; idx < 39 * 39; idx += 256) {
        int r  = idx / 39;
        int cc = idx - r * 39;
        int gh = ty0 - 3 + r;
        int gw = tx0 - 3 + cc;
        float v = 0.f;
        if (gh >= 0 && gh <= 256 && gw >= 0 && gw <= 256) {
            int gh2 = (gh == 256) ? 254 : gh;
            int gw2 = (gw == 256) ? 254 : gw;
            int co = gw2 - (tx0 - 6);
            int rbase = gh2 - 3 - (ty0 - 6);
            float vs = 0.f;
#pragma unroll
            for (int q = 0; q < 8; ++q) vs += attnS[rbase + q][co];
            if (gh2 >= 252) vs += attnS[254 - (ty0 - 6)][co];

            int ro = gh2 - (ty0 - 6);
            int cbase = gw2 - 3 - (tx0 - 6);
            float hs = 0.f;
#pragma unroll
            for (int q = 0; q < 8; ++q) hs += attnS[ro][cbase + q];
            if (gw2 >= 252) hs += attnS[ro][254 - (tx0 - 6)];

            v = (vs + hs) * 0.125f + f16f(lplane[gh2 * 256 + gw2]);
        }
        midS[r][cc] = v;
    }
    __syncthreads();

    int lw  = tid & 31;
    int lh0 = (tid >> 5) * 4;
    float acc[4] = {0.f, 0.f, 0.f, 0.f};
#pragma unroll
    for (int j = 0; j < 8; ++j) {
        float wcol[8];
#pragma unroll
        for (int i = 0; i < 8; ++i) wcol[i] = ws[i * 8 + j];
#pragma unroll
        for (int r = 0; r < 11; ++r) {
            float v = midS[lh0 + r][lw + j];
#pragma unroll
            for (int a = 0; a < 4; ++a) {
                int i = r - a;
                if (i >= 0 && i < 8) acc[a] += v * wcol[i];
            }
        }
    }
    float ip = g_invp[c];
    float bb = g_biasp[c];
#pragma unroll
    for (int a = 0; a < 4; ++a) {
        int h = ty0 + lh0 + a;
        float r = acc[a] * ip + bb;
        size_t idx = ((size_t)bc << 16) + h * 256 + tx0 + lw;
        g_dwh[idx] = h16(r);
    }
}

// ---------------------------------------------------------------------------
// Launch
// ---------------------------------------------------------------------------
extern "C" void kernel_launch(void* const* d_in, const int* in_sizes, int n_in,
                              void* d_out, int out_size)
{
    const float* x    = (const float*)d_in[0];
    const float* y    = (const float*)d_in[1];
    const float* wqkv = (const float*)d_in[2];
    const float* wl1  = (const float*)d_in[3];
    const float* g1   = (const float*)d_in[4];
    const float* b1   = (const float*)d_in[5];
    const float* m1   = (const float*)d_in[6];
    const float* v1   = (const float*)d_in[7];
    const float* wl2  = (const float*)d_in[8];
    const float* g2   = (const float*)d_in[9];
    const float* b2   = (const float*)d_in[10];
    const float* m2   = (const float*)d_in[11];
    const float* v2   = (const float*)d_in[12];
    const float* wdw  = (const float*)d_in[13];
    const float* gp   = (const float*)d_in[14];
    const float* bp   = (const float*)d_in[15];
    const float* mp   = (const float*)d_in[16];
    const float* vp   = (const float*)d_in[17];
    const float* wpw  = (const float*)d_in[18];
    const float* rpb  = (const float*)d_in[19];
    float* out = (float*)d_out;

    prep_kernel<<<1, 256>>>(g1, b1, m1, v1, g2, b2, m2, v2, gp, bp, mp, vp);
    cvt_weights<<<3584, 256>>>(wqkv, wpw, wl1, wl2);
    cvt_xy<<<dim3(32768, 2), 256>>>(x, y);

    // local branch (K=2560, 1-pass fp16, halo-padded vector gather) -> g_lh
    gemm_local_f16<<<dim3(2, 1024), 256>>>();

    // qkv (M=768, K=256, 1-pass fp16) -> g_qkvh (fp16, window-major)
    gemm_aligned<<<dim3(6, 1024), 256>>>(nullptr, 768, 256, 0);

    // tensor-core attention (4 window-heads per block) -> g_attnh (fp16)
    attn_mma<<<dim3(512, 16), 128>>>(rpb);

    // fused pools + depthwise conv + BN -> g_dwh (fp16)
    dwpool_kernel<<<dim3(64, 512), 256>>>(wdw);

    // pointwise (M=256, K=256, 1-pass fp16) -> out
    gemm_aligned<<<dim3(2, 1024), 256>>>(out, 256, 256, 1);
}